// round 5
// baseline (speedup 1.0000x reference)
#include <cuda_runtime.h>
#include <cuda_bf16.h>
#include <math.h>
#include <stdint.h>

#define D_MODEL 512
#define D_FF 2048
#define BATCH 2
#define SEQ 2048
#define NHEADS 8
#define EDIM 64
#define ROWS (BATCH*SEQ)
#define GELU_CF 0.7978845608028654f
#define WSZ  (2*D_MODEL*D_MODEL)
#define W1SZ (2*D_MODEL*D_FF)

// ---------------- f32 scratch ----------------
__device__ float g_x[ROWS*D_MODEL];
__device__ float g_xb[ROWS*D_MODEL];
__device__ float g_o[ROWS*D_MODEL];

// ---------------- pre-split weights (u16 bf16 hi/lo) ----------------
__device__ uint16_t s_Wq_h[WSZ],  s_Wq_l[WSZ];
__device__ uint16_t s_Wk_h[WSZ],  s_Wk_l[WSZ];
__device__ uint16_t s_Wv_h[WSZ],  s_Wv_l[WSZ];
__device__ uint16_t s_Wo_h[WSZ],  s_Wo_l[WSZ];
__device__ uint16_t s_W1_h[W1SZ], s_W1_l[W1SZ];
__device__ uint16_t s_W2_h[W1SZ], s_W2_l[W1SZ];

// ---------------- pre-split activations ----------------
__device__ uint16_t s_x_h[ROWS*D_MODEL],    s_x_l[ROWS*D_MODEL];
__device__ uint16_t s_xb_h[ROWS*D_MODEL],   s_xb_l[ROWS*D_MODEL];
__device__ uint16_t s_q_h[ROWS*D_MODEL],    s_q_l[ROWS*D_MODEL];
__device__ uint16_t s_k_h[ROWS*D_MODEL],    s_k_l[ROWS*D_MODEL];
__device__ uint16_t s_v_h[ROWS*D_MODEL],    s_v_l[ROWS*D_MODEL];
__device__ uint16_t s_attn_h[ROWS*D_MODEL], s_attn_l[ROWS*D_MODEL];
__device__ uint16_t s_h_h[ROWS*D_FF],       s_h_l[ROWS*D_FF];

// =======================================================================
// helpers
// =======================================================================
__device__ __forceinline__ void bsplit2(float x0, float x1, uint32_t& h, uint32_t& l) {
    __nv_bfloat162 hh = __floats2bfloat162_rn(x0, x1);
    float h0 = __bfloat162float(hh.x);
    float h1 = __bfloat162float(hh.y);
    __nv_bfloat162 ll = __floats2bfloat162_rn(x0 - h0, x1 - h1);
    h = *reinterpret_cast<uint32_t*>(&hh);
    l = *reinterpret_cast<uint32_t*>(&ll);
}

__device__ __forceinline__ void mma_bf16(float* c, const uint32_t* a, const uint32_t* b) {
    asm volatile(
        "mma.sync.aligned.m16n8k16.row.col.f32.bf16.bf16.f32 "
        "{%0,%1,%2,%3}, {%4,%5,%6,%7}, {%8,%9}, {%0,%1,%2,%3};"
        : "+f"(c[0]), "+f"(c[1]), "+f"(c[2]), "+f"(c[3])
        : "r"(a[0]), "r"(a[1]), "r"(a[2]), "r"(a[3]), "r"(b[0]), "r"(b[1]));
}

__device__ __forceinline__ uint32_t smem_u32(const void* p) {
    uint32_t a;
    asm("{ .reg .u64 t; cvta.to.shared.u64 t, %1; cvt.u32.u64 %0, t; }"
        : "=r"(a) : "l"(p));
    return a;
}

__device__ __forceinline__ void cp16(uint32_t dst, const void* src) {
    asm volatile("cp.async.cg.shared.global [%0], [%1], 16;\n" :: "r"(dst), "l"(src));
}
__device__ __forceinline__ void cp_commit() {
    asm volatile("cp.async.commit_group;\n" ::: "memory");
}
__device__ __forceinline__ void cp_wait1() {
    asm volatile("cp.async.wait_group 1;\n" ::: "memory");
}
__device__ __forceinline__ void cp_wait0() {
    asm volatile("cp.async.wait_group 0;\n" ::: "memory");
}

// =======================================================================
// split prologue kernels
// =======================================================================
__global__ __launch_bounds__(256) void split_all(
    const float* __restrict__ Wq, const float* __restrict__ Wk,
    const float* __restrict__ Wv, const float* __restrict__ Wo,
    const float* __restrict__ W1, const float* __restrict__ W2)
{
    const float* src; uint16_t *dh, *dl; int n;
    switch (blockIdx.y) {
        case 0: src = Wq; dh = s_Wq_h; dl = s_Wq_l; n = WSZ;  break;
        case 1: src = Wk; dh = s_Wk_h; dl = s_Wk_l; n = WSZ;  break;
        case 2: src = Wv; dh = s_Wv_h; dl = s_Wv_l; n = WSZ;  break;
        case 3: src = Wo; dh = s_Wo_h; dl = s_Wo_l; n = WSZ;  break;
        case 4: src = W1; dh = s_W1_h; dl = s_W1_l; n = W1SZ; break;
        default: src = W2; dh = s_W2_h; dl = s_W2_l; n = W1SZ; break;
    }
    int idx = (blockIdx.x * 256 + threadIdx.x) * 4;
    if (idx >= n) return;
    float4 v = *(const float4*)(src + idx);
    uint32_t h0, l0, h1, l1;
    bsplit2(v.x, v.y, h0, l0);
    bsplit2(v.z, v.w, h1, l1);
    *(uint32_t*)&dh[idx]     = h0;  *(uint32_t*)&dh[idx + 2] = h1;
    *(uint32_t*)&dl[idx]     = l0;  *(uint32_t*)&dl[idx + 2] = l1;
}

__global__ __launch_bounds__(256) void split_x(const float* __restrict__ x)
{
    int idx = (blockIdx.x * 256 + threadIdx.x) * 4;
    float4 v = *(const float4*)(x + idx);
    *(float4*)(g_x + idx) = v;
    uint32_t h0, l0, h1, l1;
    bsplit2(v.x, v.y, h0, l0);
    bsplit2(v.z, v.w, h1, l1);
    *(uint32_t*)&s_x_h[idx]     = h0;  *(uint32_t*)&s_x_h[idx + 2] = h1;
    *(uint32_t*)&s_x_l[idx]     = l0;  *(uint32_t*)&s_x_l[idx + 2] = l1;
}

// =======================================================================
// GEMM: pre-split A/B, cp.async double-buffered
// Tile 128x128, BK=32, 256 thr (8 warps 2x4).
// Stage layout (bytes): Ah[128*40u16]=10240 | Al=10240 | Bh[32*136u16]=8704 | Bl=8704
// =======================================================================
#define A_PITCH 40
#define B_PITCH 136
#define G_STAGE 37888
#define G_SMEM (2*G_STAGE)

// epi: 0 = bias -> split out; 1 = bias + add -> f32 out; 2 = bias + gelu -> split out
__device__ __forceinline__ void gemm_body(
    const uint16_t* __restrict__ Ah, const uint16_t* __restrict__ Al,
    const uint16_t* __restrict__ Bh, const uint16_t* __restrict__ Bl,
    const float* __restrict__ bias, const float* __restrict__ add,
    float* __restrict__ Cf, uint16_t* __restrict__ Ch, uint16_t* __restrict__ Cl,
    int N, int K, int epi, int bm, int bn, char* sm)
{
    const int tid = threadIdx.x;
    const int wid = tid >> 5;
    const int lane = tid & 31;
    const int wm = wid & 1;
    const int wn = wid >> 1;
    const int fr = lane >> 2;
    const int fkc = (lane & 3) * 2;
    const uint32_t sb = smem_u32(sm);

    float acc[4][4][4];
    #pragma unroll
    for (int tm = 0; tm < 4; tm++)
        #pragma unroll
        for (int tn = 0; tn < 4; tn++)
            #pragma unroll
            for (int i = 0; i < 4; i++) acc[tm][tn][i] = 0.f;

    const int nChunks = K >> 5;

    auto issue = [&](int st, int kt) {
        uint32_t base = sb + st * G_STAGE;
        #pragma unroll
        for (int t = 0; t < 2; t++) {
            int idx = tid + t * 256;
            int row = idx >> 2, c4 = idx & 3;
            size_t go = (size_t)(bm + row) * K + kt + c4 * 8;
            cp16(base + row * 80 + c4 * 16, Ah + go);
            cp16(base + 10240 + row * 80 + c4 * 16, Al + go);
        }
        #pragma unroll
        for (int t = 0; t < 2; t++) {
            int idx = tid + t * 256;
            int k = idx >> 4, c4 = idx & 15;
            size_t go = (size_t)(kt + k) * N + bn + c4 * 8;
            cp16(base + 20480 + k * 272 + c4 * 16, Bh + go);
            cp16(base + 29184 + k * 272 + c4 * 16, Bl + go);
        }
        cp_commit();
    };

    issue(0, 0);

    for (int chunk = 0; chunk < nChunks; chunk++) {
        if (chunk + 1 < nChunks) {
            issue((chunk + 1) & 1, (chunk + 1) << 5);
            cp_wait1();
        } else {
            cp_wait0();
        }
        __syncthreads();

        const char* stg = sm + (chunk & 1) * G_STAGE;
        const uint16_t* sAh = (const uint16_t*)(stg);
        const uint16_t* sAl = (const uint16_t*)(stg + 10240);
        const uint16_t* sBh = (const uint16_t*)(stg + 20480);
        const uint16_t* sBl = (const uint16_t*)(stg + 29184);

        #pragma unroll
        for (int ks = 0; ks < 2; ks++) {
            const int K0 = ks * 16;
            uint32_t ah[4][4], al[4][4];
            #pragma unroll
            for (int tm = 0; tm < 4; tm++) {
                int base = (wm * 64 + tm * 16 + fr) * A_PITCH + K0 + fkc;
                ah[tm][0] = *(const uint32_t*)&sAh[base];
                ah[tm][1] = *(const uint32_t*)&sAh[base + 8 * A_PITCH];
                ah[tm][2] = *(const uint32_t*)&sAh[base + 8];
                ah[tm][3] = *(const uint32_t*)&sAh[base + 8 * A_PITCH + 8];
                al[tm][0] = *(const uint32_t*)&sAl[base];
                al[tm][1] = *(const uint32_t*)&sAl[base + 8 * A_PITCH];
                al[tm][2] = *(const uint32_t*)&sAl[base + 8];
                al[tm][3] = *(const uint32_t*)&sAl[base + 8 * A_PITCH + 8];
            }
            uint32_t bh[4][2], bl[4][2];
            #pragma unroll
            for (int tn = 0; tn < 4; tn++) {
                int n = wn * 32 + tn * 8 + fr;
                int kb = (K0 + fkc) * B_PITCH + n;
                bh[tn][0] = (uint32_t)sBh[kb] | ((uint32_t)sBh[kb + B_PITCH] << 16);
                bh[tn][1] = (uint32_t)sBh[kb + 8 * B_PITCH] | ((uint32_t)sBh[kb + 9 * B_PITCH] << 16);
                bl[tn][0] = (uint32_t)sBl[kb] | ((uint32_t)sBl[kb + B_PITCH] << 16);
                bl[tn][1] = (uint32_t)sBl[kb + 8 * B_PITCH] | ((uint32_t)sBl[kb + 9 * B_PITCH] << 16);
            }
            #pragma unroll
            for (int tm = 0; tm < 4; tm++)
                #pragma unroll
                for (int tn = 0; tn < 4; tn++)
                    mma_bf16(acc[tm][tn], ah[tm], bh[tn]);
            #pragma unroll
            for (int tm = 0; tm < 4; tm++)
                #pragma unroll
                for (int tn = 0; tn < 4; tn++)
                    mma_bf16(acc[tm][tn], ah[tm], bl[tn]);
            #pragma unroll
            for (int tm = 0; tm < 4; tm++)
                #pragma unroll
                for (int tn = 0; tn < 4; tn++)
                    mma_bf16(acc[tm][tn], al[tm], bh[tn]);
        }
        __syncthreads();
    }

    #pragma unroll
    for (int tm = 0; tm < 4; tm++) {
        #pragma unroll
        for (int tn = 0; tn < 4; tn++) {
            int row0 = bm + wm * 64 + tm * 16 + fr;
            int col = bn + wn * 32 + tn * 8 + fkc;
            float b0 = bias[col], b1 = bias[col + 1];
            #pragma unroll
            for (int half = 0; half < 2; half++) {
                int row = row0 + half * 8;
                float v0 = acc[tm][tn][half * 2 + 0] + b0;
                float v1 = acc[tm][tn][half * 2 + 1] + b1;
                if (epi == 1) {
                    const float* ap = add + (size_t)row * N + col;
                    v0 += ap[0]; v1 += ap[1];
                    *(float2*)(Cf + (size_t)row * N + col) = make_float2(v0, v1);
                } else {
                    if (epi == 2) {
                        float u = v0;
                        v0 = 0.5f * u * (1.0f + tanhf(GELU_CF * (u + 0.044715f * u * u * u)));
                        u = v1;
                        v1 = 0.5f * u * (1.0f + tanhf(GELU_CF * (u + 0.044715f * u * u * u)));
                    }
                    uint32_t h, l;
                    bsplit2(v0, v1, h, l);
                    *(uint32_t*)&Ch[(size_t)row * N + col] = h;
                    *(uint32_t*)&Cl[(size_t)row * N + col] = l;
                }
            }
        }
    }
}

__global__ __launch_bounds__(256, 2) void gemm_split(
    const uint16_t* __restrict__ Ah, const uint16_t* __restrict__ Al,
    const uint16_t* __restrict__ Bh, const uint16_t* __restrict__ Bl,
    const float* __restrict__ bias, const float* __restrict__ add,
    float* __restrict__ Cf, uint16_t* __restrict__ Ch, uint16_t* __restrict__ Cl,
    int N, int K, int epi)
{
    extern __shared__ char sm[];
    gemm_body(Ah, Al, Bh, Bl, bias, add, Cf, Ch, Cl, N, K, epi,
              blockIdx.y * 128, blockIdx.x * 128, sm);
}

__global__ __launch_bounds__(256, 2) void gemm_qkv(
    const float* __restrict__ bq, const float* __restrict__ bk,
    const float* __restrict__ bv, int lw)
{
    extern __shared__ char sm[];
    const int z = blockIdx.z;
    const uint16_t *Bh, *Bl;
    const float* bias;
    uint16_t *Ch, *Cl;
    if (z == 0)      { Bh = s_Wq_h + lw; Bl = s_Wq_l + lw; bias = bq; Ch = s_q_h; Cl = s_q_l; }
    else if (z == 1) { Bh = s_Wk_h + lw; Bl = s_Wk_l + lw; bias = bk; Ch = s_k_h; Cl = s_k_l; }
    else             { Bh = s_Wv_h + lw; Bl = s_Wv_l + lw; bias = bv; Ch = s_v_h; Cl = s_v_l; }
    gemm_body(s_x_h, s_x_l, Bh, Bl, bias, nullptr, nullptr, Ch, Cl,
              D_MODEL, D_MODEL, 0, blockIdx.y * 128, blockIdx.x * 128, sm);
}

// =======================================================================
// Flash attention: pre-split Q/K/V, cp.async double-buffered K/V tiles
// Stage (bytes): Kh[64*72u16]=9216 | Kl | Vh | Vl  -> 36864; 2 stages
// =======================================================================
#define KP 72
#define F_STAGE 36864
#define F_SMEM (2*F_STAGE)

__global__ __launch_bounds__(256, 2) void flash_k(
    const float* __restrict__ tau, const float* __restrict__ delta)
{
    extern __shared__ char sm[];
    const uint32_t sb = smem_u32(sm);
    const int tid = threadIdx.x;
    const int wid = tid >> 5;
    const int lane = tid & 31;
    const int fr = lane >> 2;
    const int fkc = (lane & 3) * 2;

    const int lt = (gridDim.x - 1) - blockIdx.x;
    const int bh = blockIdx.y;
    const int b = bh >> 3, h = bh & 7;
    const int qrow0 = lt * 128;
    const int rA = qrow0 + wid * 16 + fr;
    const int rB = rA + 8;

    // Q fragments from pre-split arrays
    uint32_t qh[4][4], ql[4][4];
    #pragma unroll
    for (int ks = 0; ks < 4; ks++) {
        int e0 = ks * 16 + fkc;
        size_t oA = (size_t)(b * SEQ + rA) * D_MODEL + h * EDIM + e0;
        size_t oB = (size_t)(b * SEQ + rB) * D_MODEL + h * EDIM + e0;
        qh[ks][0] = *(const uint32_t*)&s_q_h[oA];
        qh[ks][1] = *(const uint32_t*)&s_q_h[oB];
        qh[ks][2] = *(const uint32_t*)&s_q_h[oA + 8];
        qh[ks][3] = *(const uint32_t*)&s_q_h[oB + 8];
        ql[ks][0] = *(const uint32_t*)&s_q_l[oA];
        ql[ks][1] = *(const uint32_t*)&s_q_l[oB];
        ql[ks][2] = *(const uint32_t*)&s_q_l[oA + 8];
        ql[ks][3] = *(const uint32_t*)&s_q_l[oB + 8];
    }

    float oacc[8][4];
    #pragma unroll
    for (int t = 0; t < 8; t++)
        #pragma unroll
        for (int i = 0; i < 4; i++) oacc[t][i] = 0.f;
    float m0 = -3.0e38f, m1 = -3.0e38f;
    float l0 = 0.f, l1 = 0.f;
    const float sct = 0.125f * __ldg(&tau[b]);

    const int nst = 2 * (lt + 1);

    auto issue = [&](int st_stage, int key_base) {
        uint32_t base = sb + st_stage * F_STAGE;
        #pragma unroll
        for (int t = 0; t < 2; t++) {
            int idx = tid + t * 256;
            int row = idx >> 3, c4 = idx & 7;
            size_t go = (size_t)(b * SEQ + key_base + row) * D_MODEL + h * EDIM + c4 * 8;
            uint32_t dst = base + row * 144 + c4 * 16;
            cp16(dst,          s_k_h + go);
            cp16(dst + 9216,   s_k_l + go);
            cp16(dst + 18432,  s_v_h + go);
            cp16(dst + 27648,  s_v_l + go);
        }
        cp_commit();
    };

    issue(0, 0);

    for (int st = 0; st < nst; st++) {
        const int key_base = st * 64;
        if (st + 1 < nst) {
            issue((st + 1) & 1, key_base + 64);
            cp_wait1();
        } else {
            cp_wait0();
        }
        __syncthreads();

        const char* stg = sm + (st & 1) * F_STAGE;
        const uint16_t* sKh = (const uint16_t*)(stg);
        const uint16_t* sKl = (const uint16_t*)(stg + 9216);
        const uint16_t* sVh = (const uint16_t*)(stg + 18432);
        const uint16_t* sVl = (const uint16_t*)(stg + 27648);

        // ---- S = Q K^T ----
        float s[8][4];
        #pragma unroll
        for (int t = 0; t < 8; t++)
            #pragma unroll
            for (int i = 0; i < 4; i++) s[t][i] = 0.f;

        #pragma unroll
        for (int ks = 0; ks < 4; ks++) {
            const int K0 = ks * 16;
            #pragma unroll
            for (int tn = 0; tn < 8; tn++) {
                int key = tn * 8 + fr;
                int base = key * KP + K0 + fkc;
                uint32_t bhh[2], bll[2];
                bhh[0] = *(const uint32_t*)&sKh[base];
                bhh[1] = *(const uint32_t*)&sKh[base + 8];
                bll[0] = *(const uint32_t*)&sKl[base];
                bll[1] = *(const uint32_t*)&sKl[base + 8];
                mma_bf16(s[tn], qh[ks], bhh);
                mma_bf16(s[tn], qh[ks], bll);
                mma_bf16(s[tn], ql[ks], bhh);
            }
        }

        // ---- scale + bias + mask ----
        const bool masked = (key_base + 63) > qrow0;
        #pragma unroll
        for (int tn = 0; tn < 8; tn++) {
            int key = key_base + tn * 8 + fkc;
            float2 dd = *(const float2*)(delta + b * SEQ + key);
            float d0 = 0.125f * dd.x, d1 = 0.125f * dd.y;
            s[tn][0] = fmaf(s[tn][0], sct, d0);
            s[tn][1] = fmaf(s[tn][1], sct, d1);
            s[tn][2] = fmaf(s[tn][2], sct, d0);
            s[tn][3] = fmaf(s[tn][3], sct, d1);
            if (masked) {
                if (key     > rA) s[tn][0] = -1e30f;
                if (key + 1 > rA) s[tn][1] = -1e30f;
                if (key     > rB) s[tn][2] = -1e30f;
                if (key + 1 > rB) s[tn][3] = -1e30f;
            }
        }

        // ---- online softmax ----
        float r0 = -3.0e38f, r1 = -3.0e38f;
        #pragma unroll
        for (int tn = 0; tn < 8; tn++) {
            r0 = fmaxf(r0, fmaxf(s[tn][0], s[tn][1]));
            r1 = fmaxf(r1, fmaxf(s[tn][2], s[tn][3]));
        }
        r0 = fmaxf(r0, __shfl_xor_sync(~0u, r0, 1));
        r0 = fmaxf(r0, __shfl_xor_sync(~0u, r0, 2));
        r1 = fmaxf(r1, __shfl_xor_sync(~0u, r1, 1));
        r1 = fmaxf(r1, __shfl_xor_sync(~0u, r1, 2));
        float mn0 = fmaxf(m0, r0), mn1 = fmaxf(m1, r1);
        float sc0 = expf(m0 - mn0), sc1 = expf(m1 - mn1);
        float sum0 = 0.f, sum1 = 0.f;
        #pragma unroll
        for (int tn = 0; tn < 8; tn++) {
            s[tn][0] = expf(s[tn][0] - mn0); sum0 += s[tn][0];
            s[tn][1] = expf(s[tn][1] - mn0); sum0 += s[tn][1];
            s[tn][2] = expf(s[tn][2] - mn1); sum1 += s[tn][2];
            s[tn][3] = expf(s[tn][3] - mn1); sum1 += s[tn][3];
        }
        sum0 += __shfl_xor_sync(~0u, sum0, 1);
        sum0 += __shfl_xor_sync(~0u, sum0, 2);
        sum1 += __shfl_xor_sync(~0u, sum1, 1);
        sum1 += __shfl_xor_sync(~0u, sum1, 2);
        l0 = l0 * sc0 + sum0; m0 = mn0;
        l1 = l1 * sc1 + sum1; m1 = mn1;
        #pragma unroll
        for (int t = 0; t < 8; t++) {
            oacc[t][0] *= sc0; oacc[t][1] *= sc0;
            oacc[t][2] *= sc1; oacc[t][3] *= sc1;
        }

        // ---- O += P V ----
        #pragma unroll
        for (int kc = 0; kc < 4; kc++) {
            uint32_t ah[4], al[4];
            bsplit2(s[2*kc][0],   s[2*kc][1],   ah[0], al[0]);
            bsplit2(s[2*kc][2],   s[2*kc][3],   ah[1], al[1]);
            bsplit2(s[2*kc+1][0], s[2*kc+1][1], ah[2], al[2]);
            bsplit2(s[2*kc+1][2], s[2*kc+1][3], ah[3], al[3]);
            #pragma unroll
            for (int tn2 = 0; tn2 < 8; tn2++) {
                int n = tn2 * 8 + fr;
                int k0 = kc * 16 + fkc;
                uint32_t bvh[2], bvl[2];
                bvh[0] = (uint32_t)sVh[k0*KP + n] | ((uint32_t)sVh[(k0+1)*KP + n] << 16);
                bvh[1] = (uint32_t)sVh[(k0+8)*KP + n] | ((uint32_t)sVh[(k0+9)*KP + n] << 16);
                bvl[0] = (uint32_t)sVl[k0*KP + n] | ((uint32_t)sVl[(k0+1)*KP + n] << 16);
                bvl[1] = (uint32_t)sVl[(k0+8)*KP + n] | ((uint32_t)sVl[(k0+9)*KP + n] << 16);
                mma_bf16(oacc[tn2], ah, bvh);
                mma_bf16(oacc[tn2], ah, bvl);
                mma_bf16(oacc[tn2], al, bvh);
            }
        }
        __syncthreads();
    }

    // ---- write split attn output ----
    const float inv0 = 1.0f / l0, inv1 = 1.0f / l1;
    #pragma unroll
    for (int tn2 = 0; tn2 < 8; tn2++) {
        int col = h * EDIM + tn2 * 8 + fkc;
        uint32_t h32, l32;
        bsplit2(oacc[tn2][0] * inv0, oacc[tn2][1] * inv0, h32, l32);
        size_t oA = (size_t)(b * SEQ + rA) * D_MODEL + col;
        *(uint32_t*)&s_attn_h[oA] = h32;
        *(uint32_t*)&s_attn_l[oA] = l32;
        bsplit2(oacc[tn2][2] * inv1, oacc[tn2][3] * inv1, h32, l32);
        size_t oB = (size_t)(b * SEQ + rB) * D_MODEL + col;
        *(uint32_t*)&s_attn_h[oB] = h32;
        *(uint32_t*)&s_attn_l[oB] = l32;
    }
}

// ---------------- LayerNorm (+ optional split outputs) ----------------
__global__ __launch_bounds__(128) void ln_k(
    const float* __restrict__ x, const float* __restrict__ g,
    const float* __restrict__ bb, float* __restrict__ y,
    uint16_t* __restrict__ yh, uint16_t* __restrict__ yl)
{
    const int row = blockIdx.x;
    const float* p = x + (size_t)row * D_MODEL;
    const int tid = threadIdx.x;
    float4 v = *(const float4*)(p + tid * 4);
    float s = v.x + v.y + v.z + v.w;
    __shared__ float sh[4];
    #pragma unroll
    for (int o = 16; o > 0; o >>= 1) s += __shfl_xor_sync(~0u, s, o);
    if ((tid & 31) == 0) sh[tid >> 5] = s;
    __syncthreads();
    s = sh[0] + sh[1] + sh[2] + sh[3];
    const float mean = s * (1.0f / (float)D_MODEL);
    float vs = (v.x - mean) * (v.x - mean) + (v.y - mean) * (v.y - mean)
             + (v.z - mean) * (v.z - mean) + (v.w - mean) * (v.w - mean);
    #pragma unroll
    for (int o = 16; o > 0; o >>= 1) vs += __shfl_xor_sync(~0u, vs, o);
    __syncthreads();
    if ((tid & 31) == 0) sh[tid >> 5] = vs;
    __syncthreads();
    vs = sh[0] + sh[1] + sh[2] + sh[3];
    const float rstd = rsqrtf(vs * (1.0f / (float)D_MODEL) + 1e-5f);
    const int col = tid * 4;
    const float4 gg = *(const float4*)(g + col);
    const float4 bbv = *(const float4*)(bb + col);
    float4 out;
    out.x = (v.x - mean) * rstd * gg.x + bbv.x;
    out.y = (v.y - mean) * rstd * gg.y + bbv.y;
    out.z = (v.z - mean) * rstd * gg.z + bbv.z;
    out.w = (v.w - mean) * rstd * gg.w + bbv.w;
    *(float4*)(y + (size_t)row * D_MODEL + col) = out;
    if (yh != nullptr) {
        uint32_t h0, l0, h1, l1;
        bsplit2(out.x, out.y, h0, l0);
        bsplit2(out.z, out.w, h1, l1);
        size_t o = (size_t)row * D_MODEL + col;
        *(uint32_t*)&yh[o]     = h0;  *(uint32_t*)&yh[o + 2] = h1;
        *(uint32_t*)&yl[o]     = l0;  *(uint32_t*)&yl[o + 2] = l1;
    }
}

// ---------------- orchestration ----------------
extern "C" void kernel_launch(void* const* d_in, const int* in_sizes, int n_in,
                              void* d_out, int out_size)
{
    const float* x_in  = (const float*)d_in[0];
    const float* tau   = (const float*)d_in[1];
    const float* delta = (const float*)d_in[2];
    const float* Wq = (const float*)d_in[4];
    const float* bq = (const float*)d_in[5];
    const float* Wk = (const float*)d_in[6];
    const float* bk = (const float*)d_in[7];
    const float* Wv = (const float*)d_in[8];
    const float* bv = (const float*)d_in[9];
    const float* Wo = (const float*)d_in[10];
    const float* bo = (const float*)d_in[11];
    const float* W1 = (const float*)d_in[12];
    const float* b1 = (const float*)d_in[13];
    const float* W2 = (const float*)d_in[14];
    const float* b2 = (const float*)d_in[15];
    const float* ln1g = (const float*)d_in[16];
    const float* ln1b = (const float*)d_in[17];
    const float* ln2g = (const float*)d_in[18];
    const float* ln2b = (const float*)d_in[19];
    const float* lnfg = (const float*)d_in[20];
    const float* lnfb = (const float*)d_in[21];

    float *gx, *gxb, *go;
    cudaGetSymbolAddress((void**)&gx,  g_x);
    cudaGetSymbolAddress((void**)&gxb, g_xb);
    cudaGetSymbolAddress((void**)&go,  g_o);

    uint16_t *axh, *axl, *axbh, *axbl, *ahh, *ahl, *aath, *aatl;
    cudaGetSymbolAddress((void**)&axh,  s_x_h);
    cudaGetSymbolAddress((void**)&axl,  s_x_l);
    cudaGetSymbolAddress((void**)&axbh, s_xb_h);
    cudaGetSymbolAddress((void**)&axbl, s_xb_l);
    cudaGetSymbolAddress((void**)&ahh,  s_h_h);
    cudaGetSymbolAddress((void**)&ahl,  s_h_l);
    cudaGetSymbolAddress((void**)&aath, s_attn_h);
    cudaGetSymbolAddress((void**)&aatl, s_attn_l);

    uint16_t *wo_h, *wo_l, *w1_h, *w1_l, *w2_h, *w2_l;
    cudaGetSymbolAddress((void**)&wo_h, s_Wo_h);
    cudaGetSymbolAddress((void**)&wo_l, s_Wo_l);
    cudaGetSymbolAddress((void**)&w1_h, s_W1_h);
    cudaGetSymbolAddress((void**)&w1_l, s_W1_l);
    cudaGetSymbolAddress((void**)&w2_h, s_W2_h);
    cudaGetSymbolAddress((void**)&w2_l, s_W2_l);

    cudaFuncSetAttribute(gemm_split, cudaFuncAttributeMaxDynamicSharedMemorySize, G_SMEM);
    cudaFuncSetAttribute(gemm_qkv,   cudaFuncAttributeMaxDynamicSharedMemorySize, G_SMEM);
    cudaFuncSetAttribute(flash_k,    cudaFuncAttributeMaxDynamicSharedMemorySize, F_SMEM);

    // prologue: split weights + input
    split_all<<<dim3(W1SZ / 1024, 6), 256>>>(Wq, Wk, Wv, Wo, W1, W2);
    split_x<<<ROWS * D_MODEL / 1024, 256>>>(x_in);

    const dim3 gProj(D_MODEL / 128, ROWS / 128);       // (4, 32)
    const dim3 gQKV(D_MODEL / 128, ROWS / 128, 3);     // (4, 32, 3)
    const dim3 gFF1(D_FF / 128, ROWS / 128);           // (16, 32)
    const dim3 gFlash(SEQ / 128, BATCH * NHEADS);      // (16, 16)

    for (int l = 0; l < 2; l++) {
        const int wOff   = l * D_MODEL * D_MODEL;
        const int w1Off  = l * D_MODEL * D_FF;
        const size_t bOff  = (size_t)l * D_MODEL;
        const size_t b1Off = (size_t)l * D_FF;

        gemm_qkv<<<gQKV, 256, G_SMEM>>>(bq + bOff, bk + bOff, bv + bOff, wOff);

        flash_k<<<gFlash, 256, F_SMEM>>>(tau, delta);

        gemm_split<<<gProj, 256, G_SMEM>>>(aath, aatl, wo_h + wOff, wo_l + wOff,
                                           bo + bOff, gx, gx, nullptr, nullptr,
                                           D_MODEL, D_MODEL, 1);
        ln_k<<<ROWS, 128>>>(gx, ln1g + bOff, ln1b + bOff, gxb, axbh, axbl);

        gemm_split<<<gFF1, 256, G_SMEM>>>(axbh, axbl, w1_h + w1Off, w1_l + w1Off,
                                          b1 + b1Off, nullptr, nullptr, ahh, ahl,
                                          D_FF, D_MODEL, 2);
        gemm_split<<<gProj, 256, G_SMEM>>>(ahh, ahl, w2_h + w1Off, w2_l + w1Off,
                                           b2 + bOff, gxb, go, nullptr, nullptr,
                                           D_MODEL, D_FF, 1);
        ln_k<<<ROWS, 128>>>(go, ln2g + bOff, ln2b + bOff, gx, axh, axl);
    }
    ln_k<<<ROWS, 128>>>(gx, lnfg, lnfb, (float*)d_out, nullptr, nullptr);
}

// round 6
// speedup vs baseline: 1.1950x; 1.1950x over previous
#include <cuda_runtime.h>
#include <cuda_bf16.h>
#include <math.h>
#include <stdint.h>

#define D_MODEL 512
#define D_FF 2048
#define BATCH 2
#define SEQ 2048
#define NHEADS 8
#define EDIM 64
#define ROWS (BATCH*SEQ)
#define BH (BATCH*NHEADS)
#define GELU_CF 0.7978845608028654f
#define WSZ  (2*D_MODEL*D_MODEL)
#define W1SZ (2*D_MODEL*D_FF)

// ---------------- f32 scratch ----------------
__device__ float g_x[ROWS*D_MODEL];
__device__ float g_xb[ROWS*D_MODEL];
__device__ float g_o[ROWS*D_MODEL];
__device__ float g_po0[ROWS*D_MODEL];
__device__ float g_po1[ROWS*D_MODEL];
__device__ float g_ml0[BH*SEQ*2];
__device__ float g_ml1[BH*SEQ*2];

// ---------------- pre-split TRANSPOSED weights ([layer][N][K], u16 bf16 hi/lo) ----
__device__ uint16_t s_Wq_h[WSZ],  s_Wq_l[WSZ];
__device__ uint16_t s_Wk_h[WSZ],  s_Wk_l[WSZ];
__device__ uint16_t s_Wv_h[WSZ],  s_Wv_l[WSZ];
__device__ uint16_t s_Wo_h[WSZ],  s_Wo_l[WSZ];
__device__ uint16_t s_W1_h[W1SZ], s_W1_l[W1SZ];
__device__ uint16_t s_W2_h[W1SZ], s_W2_l[W1SZ];

// ---------------- pre-split activations ----------------
__device__ uint16_t s_x_h[ROWS*D_MODEL],    s_x_l[ROWS*D_MODEL];
__device__ uint16_t s_xb_h[ROWS*D_MODEL],   s_xb_l[ROWS*D_MODEL];
__device__ uint16_t s_q_h[ROWS*D_MODEL],    s_q_l[ROWS*D_MODEL];
__device__ uint16_t s_k_h[ROWS*D_MODEL],    s_k_l[ROWS*D_MODEL];
__device__ uint16_t s_v_h[ROWS*D_MODEL],    s_v_l[ROWS*D_MODEL];
__device__ uint16_t s_vT_h[ROWS*D_MODEL],   s_vT_l[ROWS*D_MODEL];  // [bh][e][tok]
__device__ uint16_t s_attn_h[ROWS*D_MODEL], s_attn_l[ROWS*D_MODEL];
__device__ uint16_t s_h_h[ROWS*D_FF],       s_h_l[ROWS*D_FF];

// =======================================================================
// helpers
// =======================================================================
__device__ __forceinline__ void bsplit2(float x0, float x1, uint32_t& h, uint32_t& l) {
    __nv_bfloat162 hh = __floats2bfloat162_rn(x0, x1);
    float h0 = __bfloat162float(hh.x);
    float h1 = __bfloat162float(hh.y);
    __nv_bfloat162 ll = __floats2bfloat162_rn(x0 - h0, x1 - h1);
    h = *reinterpret_cast<uint32_t*>(&hh);
    l = *reinterpret_cast<uint32_t*>(&ll);
}

__device__ __forceinline__ void mma_bf16(float* c, const uint32_t* a, const uint32_t* b) {
    asm volatile(
        "mma.sync.aligned.m16n8k16.row.col.f32.bf16.bf16.f32 "
        "{%0,%1,%2,%3}, {%4,%5,%6,%7}, {%8,%9}, {%0,%1,%2,%3};"
        : "+f"(c[0]), "+f"(c[1]), "+f"(c[2]), "+f"(c[3])
        : "r"(a[0]), "r"(a[1]), "r"(a[2]), "r"(a[3]), "r"(b[0]), "r"(b[1]));
}

__device__ __forceinline__ uint32_t smem_u32(const void* p) {
    uint32_t a;
    asm("{ .reg .u64 t; cvta.to.shared.u64 t, %1; cvt.u32.u64 %0, t; }"
        : "=r"(a) : "l"(p));
    return a;
}

__device__ __forceinline__ void cp16(uint32_t dst, const void* src) {
    asm volatile("cp.async.cg.shared.global [%0], [%1], 16;\n" :: "r"(dst), "l"(src));
}
__device__ __forceinline__ void cp_commit() {
    asm volatile("cp.async.commit_group;\n" ::: "memory");
}
__device__ __forceinline__ void cp_wait1() {
    asm volatile("cp.async.wait_group 1;\n" ::: "memory");
}
__device__ __forceinline__ void cp_wait0() {
    asm volatile("cp.async.wait_group 0;\n" ::: "memory");
}

// =======================================================================
// prologue: transpose + split weights;  split input x
// =======================================================================
__global__ __launch_bounds__(256) void transp_split(
    const float* __restrict__ Wq, const float* __restrict__ Wk,
    const float* __restrict__ Wv, const float* __restrict__ Wo,
    const float* __restrict__ W1, const float* __restrict__ W2)
{
    const int w = blockIdx.z >> 1, layer = blockIdx.z & 1;
    const float* src; uint16_t *dh, *dl; int K, N;
    switch (w) {
        case 0: src = Wq; dh = s_Wq_h; dl = s_Wq_l; K = 512;  N = 512;  break;
        case 1: src = Wk; dh = s_Wk_h; dl = s_Wk_l; K = 512;  N = 512;  break;
        case 2: src = Wv; dh = s_Wv_h; dl = s_Wv_l; K = 512;  N = 512;  break;
        case 3: src = Wo; dh = s_Wo_h; dl = s_Wo_l; K = 512;  N = 512;  break;
        case 4: src = W1; dh = s_W1_h; dl = s_W1_l; K = 512;  N = 2048; break;
        default: src = W2; dh = s_W2_h; dl = s_W2_l; K = 2048; N = 512; break;
    }
    const int k0 = blockIdx.x * 32, n0 = blockIdx.y * 32;
    if (k0 >= K || n0 >= N) return;
    src += (size_t)layer * K * N;
    dh  += (size_t)layer * K * N;
    dl  += (size_t)layer * K * N;

    __shared__ float t[32][33];
    const int tid = threadIdx.x;
    const int tx = tid & 31, ty = tid >> 5;
    #pragma unroll
    for (int i = 0; i < 4; i++) {
        int k = ty + i * 8;
        t[k][tx] = src[(size_t)(k0 + k) * N + n0 + tx];
    }
    __syncthreads();
    const int n = tid >> 3, kq = tid & 7;
    float a0 = t[kq*4+0][n], a1 = t[kq*4+1][n], a2 = t[kq*4+2][n], a3 = t[kq*4+3][n];
    uint32_t h0, l0, h1, l1;
    bsplit2(a0, a1, h0, l0);
    bsplit2(a2, a3, h1, l1);
    size_t o = (size_t)(n0 + n) * K + k0 + kq * 4;
    *(uint32_t*)&dh[o]     = h0;  *(uint32_t*)&dh[o + 2] = h1;
    *(uint32_t*)&dl[o]     = l0;  *(uint32_t*)&dl[o + 2] = l1;
}

__global__ __launch_bounds__(256) void split_x(const float* __restrict__ x)
{
    int idx = (blockIdx.x * 256 + threadIdx.x) * 4;
    float4 v = *(const float4*)(x + idx);
    *(float4*)(g_x + idx) = v;
    uint32_t h0, l0, h1, l1;
    bsplit2(v.x, v.y, h0, l0);
    bsplit2(v.z, v.w, h1, l1);
    *(uint32_t*)&s_x_h[idx]     = h0;  *(uint32_t*)&s_x_h[idx + 2] = h1;
    *(uint32_t*)&s_x_l[idx]     = l0;  *(uint32_t*)&s_x_l[idx + 2] = l1;
}

// V transpose: s_v [tok][h*64+e] -> s_vT [bh][e][tok]
__global__ __launch_bounds__(256) void vtransp()
{
    __shared__ uint16_t tt[32][66];
    const int bh = blockIdx.y;
    const int b = bh >> 3, h = bh & 7;
    const int tok0 = blockIdx.x * 32;
    const int tid = threadIdx.x;
    #pragma unroll
    for (int pass = 0; pass < 2; pass++) {
        const uint16_t* src = pass ? s_v_l : s_v_h;
        uint16_t* dst = pass ? s_vT_l : s_vT_h;
        #pragma unroll
        for (int i = 0; i < 4; i++) {
            int idx = tid + i * 256;           // 32 toks x 32 u32
            int r = idx >> 5, c = idx & 31;
            uint32_t v = *(const uint32_t*)&src[(size_t)(b * SEQ + tok0 + r) * D_MODEL + h * 64 + c * 2];
            *(uint32_t*)&tt[r][c * 2] = v;
        }
        __syncthreads();
        #pragma unroll
        for (int i = 0; i < 4; i++) {
            int idx = tid + i * 256;           // 64 e x 16 u32
            int e = idx >> 4, t2 = idx & 15;
            uint32_t v = (uint32_t)tt[t2 * 2][e] | ((uint32_t)tt[t2 * 2 + 1][e] << 16);
            *(uint32_t*)&dst[((size_t)bh * EDIM + e) * SEQ + tok0 + t2 * 2] = v;
        }
        __syncthreads();
    }
}

// =======================================================================
// GEMM: A row-major [M][K], B = transposed weights [N][K]; both n/row-major.
// Tile 128x128, BK=32, 256 thr. cp.async double-buffered.
// Stage: Ah(10240) Al(10240) Bh(10240) Bl(10240) = 40960
// =======================================================================
#define A_PITCH 40
#define G_STAGE 40960
#define G_SMEM (2*G_STAGE)

// epi: 0 = bias -> split out; 1 = bias + add -> f32 out; 2 = bias + gelu -> split out
__device__ __forceinline__ void gemm_body(
    const uint16_t* __restrict__ Ah, const uint16_t* __restrict__ Al,
    const uint16_t* __restrict__ Bh, const uint16_t* __restrict__ Bl,
    const float* __restrict__ bias, const float* __restrict__ add,
    float* __restrict__ Cf, uint16_t* __restrict__ Ch, uint16_t* __restrict__ Cl,
    int N, int K, int epi, int bm, int bn, char* sm)
{
    const int tid = threadIdx.x;
    const int wid = tid >> 5;
    const int lane = tid & 31;
    const int wm = wid & 1;
    const int wn = wid >> 1;
    const int fr = lane >> 2;
    const int fkc = (lane & 3) * 2;
    const uint32_t sb = smem_u32(sm);

    float acc[4][4][4];
    #pragma unroll
    for (int tm = 0; tm < 4; tm++)
        #pragma unroll
        for (int tn = 0; tn < 4; tn++)
            #pragma unroll
            for (int i = 0; i < 4; i++) acc[tm][tn][i] = 0.f;

    const int nChunks = K >> 5;

    auto issue = [&](int st, int kt) {
        uint32_t base = sb + st * G_STAGE;
        #pragma unroll
        for (int t = 0; t < 2; t++) {
            int idx = tid + t * 256;
            int row = idx >> 2, c4 = idx & 3;
            size_t ga = (size_t)(bm + row) * K + kt + c4 * 8;
            cp16(base + row * 80 + c4 * 16, Ah + ga);
            cp16(base + 10240 + row * 80 + c4 * 16, Al + ga);
            size_t gb = (size_t)(bn + row) * K + kt + c4 * 8;
            cp16(base + 20480 + row * 80 + c4 * 16, Bh + gb);
            cp16(base + 30720 + row * 80 + c4 * 16, Bl + gb);
        }
        cp_commit();
    };

    issue(0, 0);

    for (int chunk = 0; chunk < nChunks; chunk++) {
        if (chunk + 1 < nChunks) {
            issue((chunk + 1) & 1, (chunk + 1) << 5);
            cp_wait1();
        } else {
            cp_wait0();
        }
        __syncthreads();

        const char* stg = sm + (chunk & 1) * G_STAGE;
        const uint16_t* sAh = (const uint16_t*)(stg);
        const uint16_t* sAl = (const uint16_t*)(stg + 10240);
        const uint16_t* sBh = (const uint16_t*)(stg + 20480);
        const uint16_t* sBl = (const uint16_t*)(stg + 30720);

        #pragma unroll
        for (int ks = 0; ks < 2; ks++) {
            const int K0 = ks * 16;
            uint32_t ah[4][4], al[4][4];
            #pragma unroll
            for (int tm = 0; tm < 4; tm++) {
                int base = (wm * 64 + tm * 16 + fr) * A_PITCH + K0 + fkc;
                ah[tm][0] = *(const uint32_t*)&sAh[base];
                ah[tm][1] = *(const uint32_t*)&sAh[base + 8 * A_PITCH];
                ah[tm][2] = *(const uint32_t*)&sAh[base + 8];
                ah[tm][3] = *(const uint32_t*)&sAh[base + 8 * A_PITCH + 8];
                al[tm][0] = *(const uint32_t*)&sAl[base];
                al[tm][1] = *(const uint32_t*)&sAl[base + 8 * A_PITCH];
                al[tm][2] = *(const uint32_t*)&sAl[base + 8];
                al[tm][3] = *(const uint32_t*)&sAl[base + 8 * A_PITCH + 8];
            }
            uint32_t bh[4][2], bl[4][2];
            #pragma unroll
            for (int tn = 0; tn < 4; tn++) {
                int nb = (wn * 32 + tn * 8 + fr) * A_PITCH + K0 + fkc;
                bh[tn][0] = *(const uint32_t*)&sBh[nb];
                bh[tn][1] = *(const uint32_t*)&sBh[nb + 8];
                bl[tn][0] = *(const uint32_t*)&sBl[nb];
                bl[tn][1] = *(const uint32_t*)&sBl[nb + 8];
            }
            #pragma unroll
            for (int tm = 0; tm < 4; tm++)
                #pragma unroll
                for (int tn = 0; tn < 4; tn++)
                    mma_bf16(acc[tm][tn], ah[tm], bh[tn]);
            #pragma unroll
            for (int tm = 0; tm < 4; tm++)
                #pragma unroll
                for (int tn = 0; tn < 4; tn++)
                    mma_bf16(acc[tm][tn], ah[tm], bl[tn]);
            #pragma unroll
            for (int tm = 0; tm < 4; tm++)
                #pragma unroll
                for (int tn = 0; tn < 4; tn++)
                    mma_bf16(acc[tm][tn], al[tm], bh[tn]);
        }
        __syncthreads();
    }

    #pragma unroll
    for (int tm = 0; tm < 4; tm++) {
        #pragma unroll
        for (int tn = 0; tn < 4; tn++) {
            int row0 = bm + wm * 64 + tm * 16 + fr;
            int col = bn + wn * 32 + tn * 8 + fkc;
            float b0 = bias[col], b1 = bias[col + 1];
            #pragma unroll
            for (int half = 0; half < 2; half++) {
                int row = row0 + half * 8;
                float v0 = acc[tm][tn][half * 2 + 0] + b0;
                float v1 = acc[tm][tn][half * 2 + 1] + b1;
                if (epi == 1) {
                    const float* ap = add + (size_t)row * N + col;
                    v0 += ap[0]; v1 += ap[1];
                    *(float2*)(Cf + (size_t)row * N + col) = make_float2(v0, v1);
                } else {
                    if (epi == 2) {
                        float u = v0;
                        v0 = 0.5f * u * (1.0f + tanhf(GELU_CF * (u + 0.044715f * u * u * u)));
                        u = v1;
                        v1 = 0.5f * u * (1.0f + tanhf(GELU_CF * (u + 0.044715f * u * u * u)));
                    }
                    uint32_t h, l;
                    bsplit2(v0, v1, h, l);
                    *(uint32_t*)&Ch[(size_t)row * N + col] = h;
                    *(uint32_t*)&Cl[(size_t)row * N + col] = l;
                }
            }
        }
    }
}

__global__ __launch_bounds__(256, 2) void gemm_split(
    const uint16_t* __restrict__ Ah, const uint16_t* __restrict__ Al,
    const uint16_t* __restrict__ Bh, const uint16_t* __restrict__ Bl,
    const float* __restrict__ bias, const float* __restrict__ add,
    float* __restrict__ Cf, uint16_t* __restrict__ Ch, uint16_t* __restrict__ Cl,
    int N, int K, int epi)
{
    extern __shared__ char sm[];
    gemm_body(Ah, Al, Bh, Bl, bias, add, Cf, Ch, Cl, N, K, epi,
              blockIdx.y * 128, blockIdx.x * 128, sm);
}

__global__ __launch_bounds__(256, 2) void gemm_qkv(
    const float* __restrict__ bq, const float* __restrict__ bk,
    const float* __restrict__ bv, int lw)
{
    extern __shared__ char sm[];
    const int z = blockIdx.z;
    const uint16_t *Bh, *Bl;
    const float* bias;
    uint16_t *Ch, *Cl;
    if (z == 0)      { Bh = s_Wq_h + lw; Bl = s_Wq_l + lw; bias = bq; Ch = s_q_h; Cl = s_q_l; }
    else if (z == 1) { Bh = s_Wk_h + lw; Bl = s_Wk_l + lw; bias = bk; Ch = s_k_h; Cl = s_k_l; }
    else             { Bh = s_Wv_h + lw; Bl = s_Wv_l + lw; bias = bv; Ch = s_v_h; Cl = s_v_l; }
    gemm_body(s_x_h, s_x_l, Bh, Bl, bias, nullptr, nullptr, Ch, Cl,
              D_MODEL, D_MODEL, 0, blockIdx.y * 128, blockIdx.x * 128, sm);
}

// =======================================================================
// Flash attention, 2-way split-KV. Block: 128 q-rows x half the key range.
// Stage: Kh(9216) Kl(9216) VTh(9216) VTl(9216) = 36864; 2 stages.
// =======================================================================
#define KP 72
#define F_STAGE 36864
#define F_SMEM (2*F_STAGE)

__global__ __launch_bounds__(256, 2) void flash_split(
    const float* __restrict__ tau, const float* __restrict__ delta)
{
    extern __shared__ char sm[];
    const uint32_t sb = smem_u32(sm);
    const int tid = threadIdx.x;
    const int wid = tid >> 5;
    const int lane = tid & 31;
    const int fr = lane >> 2;
    const int fkc = (lane & 3) * 2;

    const int nLt = gridDim.x >> 1;
    const int lt = nLt - 1 - (blockIdx.x >> 1);
    const int z = blockIdx.x & 1;
    const int bh = blockIdx.y;
    const int b = bh >> 3, h = bh & 7;
    const int qrow0 = lt * 128;
    const int rA = qrow0 + wid * 16 + fr;
    const int rB = rA + 8;

    uint32_t qh[4][4], ql[4][4];
    #pragma unroll
    for (int ks = 0; ks < 4; ks++) {
        int e0 = ks * 16 + fkc;
        size_t oA = (size_t)(b * SEQ + rA) * D_MODEL + h * EDIM + e0;
        size_t oB = (size_t)(b * SEQ + rB) * D_MODEL + h * EDIM + e0;
        qh[ks][0] = *(const uint32_t*)&s_q_h[oA];
        qh[ks][1] = *(const uint32_t*)&s_q_h[oB];
        qh[ks][2] = *(const uint32_t*)&s_q_h[oA + 8];
        qh[ks][3] = *(const uint32_t*)&s_q_h[oB + 8];
        ql[ks][0] = *(const uint32_t*)&s_q_l[oA];
        ql[ks][1] = *(const uint32_t*)&s_q_l[oB];
        ql[ks][2] = *(const uint32_t*)&s_q_l[oA + 8];
        ql[ks][3] = *(const uint32_t*)&s_q_l[oB + 8];
    }

    float oacc[8][4];
    #pragma unroll
    for (int t = 0; t < 8; t++)
        #pragma unroll
        for (int i = 0; i < 4; i++) oacc[t][i] = 0.f;
    float m0 = -3.0e38f, m1 = -3.0e38f;
    float l0 = 0.f, l1 = 0.f;
    const float sct = 0.125f * __ldg(&tau[b]);

    const int stStart = z * (lt + 1);
    const int nTiles = lt + 1;

    auto issue = [&](int stage, int key_base) {
        uint32_t base = sb + stage * F_STAGE;
        #pragma unroll
        for (int t = 0; t < 2; t++) {
            int idx = tid + t * 256;
            int row = idx >> 3, c8 = idx & 7;
            size_t gk = (size_t)(b * SEQ + key_base + row) * D_MODEL + h * EDIM + c8 * 8;
            uint32_t dk = base + row * 144 + c8 * 16;
            cp16(dk, s_k_h + gk);
            cp16(dk + 9216, s_k_l + gk);
            size_t gv = ((size_t)bh * EDIM + row) * SEQ + key_base + c8 * 8;
            uint32_t dv = base + 18432 + row * 144 + c8 * 16;
            cp16(dv, s_vT_h + gv);
            cp16(dv + 9216, s_vT_l + gv);
        }
        cp_commit();
    };

    issue(0, stStart * 64);

    for (int it = 0; it < nTiles; it++) {
        const int key_base = (stStart + it) * 64;
        if (it + 1 < nTiles) {
            issue((it + 1) & 1, key_base + 64);
            cp_wait1();
        } else {
            cp_wait0();
        }
        __syncthreads();

        const char* stg = sm + (it & 1) * F_STAGE;
        const uint16_t* sKh  = (const uint16_t*)(stg);
        const uint16_t* sKl  = (const uint16_t*)(stg + 9216);
        const uint16_t* sVTh = (const uint16_t*)(stg + 18432);
        const uint16_t* sVTl = (const uint16_t*)(stg + 27648);

        // ---- S = Q K^T ----
        float s[8][4];
        #pragma unroll
        for (int t = 0; t < 8; t++)
            #pragma unroll
            for (int i = 0; i < 4; i++) s[t][i] = 0.f;

        #pragma unroll
        for (int ks = 0; ks < 4; ks++) {
            const int K0 = ks * 16;
            #pragma unroll
            for (int tn = 0; tn < 8; tn++) {
                int base = (tn * 8 + fr) * KP + K0 + fkc;
                uint32_t bhh[2], bll[2];
                bhh[0] = *(const uint32_t*)&sKh[base];
                bhh[1] = *(const uint32_t*)&sKh[base + 8];
                bll[0] = *(const uint32_t*)&sKl[base];
                bll[1] = *(const uint32_t*)&sKl[base + 8];
                mma_bf16(s[tn], qh[ks], bhh);
                mma_bf16(s[tn], qh[ks], bll);
                mma_bf16(s[tn], ql[ks], bhh);
            }
        }

        // ---- scale + bias + mask ----
        const bool masked = (key_base + 63) > qrow0;
        #pragma unroll
        for (int tn = 0; tn < 8; tn++) {
            int key = key_base + tn * 8 + fkc;
            float2 dd = *(const float2*)(delta + b * SEQ + key);
            float d0 = 0.125f * dd.x, d1 = 0.125f * dd.y;
            s[tn][0] = fmaf(s[tn][0], sct, d0);
            s[tn][1] = fmaf(s[tn][1], sct, d1);
            s[tn][2] = fmaf(s[tn][2], sct, d0);
            s[tn][3] = fmaf(s[tn][3], sct, d1);
            if (masked) {
                if (key     > rA) s[tn][0] = -1e30f;
                if (key + 1 > rA) s[tn][1] = -1e30f;
                if (key     > rB) s[tn][2] = -1e30f;
                if (key + 1 > rB) s[tn][3] = -1e30f;
            }
        }

        // ---- online softmax ----
        float r0 = -3.0e38f, r1 = -3.0e38f;
        #pragma unroll
        for (int tn = 0; tn < 8; tn++) {
            r0 = fmaxf(r0, fmaxf(s[tn][0], s[tn][1]));
            r1 = fmaxf(r1, fmaxf(s[tn][2], s[tn][3]));
        }
        r0 = fmaxf(r0, __shfl_xor_sync(~0u, r0, 1));
        r0 = fmaxf(r0, __shfl_xor_sync(~0u, r0, 2));
        r1 = fmaxf(r1, __shfl_xor_sync(~0u, r1, 1));
        r1 = fmaxf(r1, __shfl_xor_sync(~0u, r1, 2));
        float mn0 = fmaxf(m0, r0), mn1 = fmaxf(m1, r1);
        float sc0 = __expf(m0 - mn0), sc1 = __expf(m1 - mn1);
        float sum0 = 0.f, sum1 = 0.f;
        #pragma unroll
        for (int tn = 0; tn < 8; tn++) {
            s[tn][0] = __expf(s[tn][0] - mn0); sum0 += s[tn][0];
            s[tn][1] = __expf(s[tn][1] - mn0); sum0 += s[tn][1];
            s[tn][2] = __expf(s[tn][2] - mn1); sum1 += s[tn][2];
            s[tn][3] = __expf(s[tn][3] - mn1); sum1 += s[tn][3];
        }
        sum0 += __shfl_xor_sync(~0u, sum0, 1);
        sum0 += __shfl_xor_sync(~0u, sum0, 2);
        sum1 += __shfl_xor_sync(~0u, sum1, 1);
        sum1 += __shfl_xor_sync(~0u, sum1, 2);
        l0 = l0 * sc0 + sum0; m0 = mn0;
        l1 = l1 * sc1 + sum1; m1 = mn1;
        #pragma unroll
        for (int t = 0; t < 8; t++) {
            oacc[t][0] *= sc0; oacc[t][1] *= sc0;
            oacc[t][2] *= sc1; oacc[t][3] *= sc1;
        }

        // ---- O += P V  (V^T smem: aligned u32 frags) ----
        #pragma unroll
        for (int kc = 0; kc < 4; kc++) {
            uint32_t ah[4], al[4];
            bsplit2(s[2*kc][0],   s[2*kc][1],   ah[0], al[0]);
            bsplit2(s[2*kc][2],   s[2*kc][3],   ah[1], al[1]);
            bsplit2(s[2*kc+1][0], s[2*kc+1][1], ah[2], al[2]);
            bsplit2(s[2*kc+1][2], s[2*kc+1][3], ah[3], al[3]);
            #pragma unroll
            for (int tn2 = 0; tn2 < 8; tn2++) {
                int vb = (tn2 * 8 + fr) * KP + kc * 16 + fkc;
                uint32_t bvh[2], bvl[2];
                bvh[0] = *(const uint32_t*)&sVTh[vb];
                bvh[1] = *(const uint32_t*)&sVTh[vb + 8];
                bvl[0] = *(const uint32_t*)&sVTl[vb];
                bvl[1] = *(const uint32_t*)&sVTl[vb + 8];
                mma_bf16(oacc[tn2], ah, bvh);
                mma_bf16(oacc[tn2], ah, bvl);
                mma_bf16(oacc[tn2], al, bvh);
            }
        }
        __syncthreads();
    }

    // ---- write partials (unnormalized O, plus m/l) ----
    float* po = z ? g_po1 : g_po0;
    float* ml = z ? g_ml1 : g_ml0;
    #pragma unroll
    for (int tn2 = 0; tn2 < 8; tn2++) {
        int col = h * EDIM + tn2 * 8 + fkc;
        *(float2*)&po[(size_t)(b * SEQ + rA) * D_MODEL + col] = make_float2(oacc[tn2][0], oacc[tn2][1]);
        *(float2*)&po[(size_t)(b * SEQ + rB) * D_MODEL + col] = make_float2(oacc[tn2][2], oacc[tn2][3]);
    }
    if ((lane & 3) == 0) {
        *(float2*)&ml[(size_t)(bh * SEQ + rA) * 2] = make_float2(m0, l0);
        *(float2*)&ml[(size_t)(bh * SEQ + rB) * 2] = make_float2(m1, l1);
    }
}

// merge split-KV partials -> split attn output
__global__ __launch_bounds__(256) void merge_k()
{
    const int idx2 = (blockIdx.x * 256 + threadIdx.x) * 2;
    const int r = idx2 >> 9;
    const int d = idx2 & 511;
    const int bh = ((r >> 11) << 3) | (d >> 6);
    const int srow = r & (SEQ - 1);
    float2 ml0 = *(float2*)&g_ml0[(size_t)(bh * SEQ + srow) * 2];
    float2 ml1 = *(float2*)&g_ml1[(size_t)(bh * SEQ + srow) * 2];
    float M = fmaxf(ml0.x, ml1.x);
    float w0 = __expf(ml0.x - M), w1 = __expf(ml1.x - M);
    float inv = 1.0f / (ml0.y * w0 + ml1.y * w1);
    float2 p0 = *(float2*)&g_po0[idx2];
    float2 p1 = *(float2*)&g_po1[idx2];
    float v0 = (p0.x * w0 + p1.x * w1) * inv;
    float v1 = (p0.y * w0 + p1.y * w1) * inv;
    uint32_t hh, ll;
    bsplit2(v0, v1, hh, ll);
    *(uint32_t*)&s_attn_h[idx2] = hh;
    *(uint32_t*)&s_attn_l[idx2] = ll;
}

// ---------------- LayerNorm (+ optional split outputs) ----------------
__global__ __launch_bounds__(128) void ln_k(
    const float* __restrict__ x, const float* __restrict__ g,
    const float* __restrict__ bb, float* __restrict__ y,
    uint16_t* __restrict__ yh, uint16_t* __restrict__ yl)
{
    const int row = blockIdx.x;
    const float* p = x + (size_t)row * D_MODEL;
    const int tid = threadIdx.x;
    float4 v = *(const float4*)(p + tid * 4);
    float s = v.x + v.y + v.z + v.w;
    __shared__ float sh[4];
    #pragma unroll
    for (int o = 16; o > 0; o >>= 1) s += __shfl_xor_sync(~0u, s, o);
    if ((tid & 31) == 0) sh[tid >> 5] = s;
    __syncthreads();
    s = sh[0] + sh[1] + sh[2] + sh[3];
    const float mean = s * (1.0f / (float)D_MODEL);
    float vs = (v.x - mean) * (v.x - mean) + (v.y - mean) * (v.y - mean)
             + (v.z - mean) * (v.z - mean) + (v.w - mean) * (v.w - mean);
    #pragma unroll
    for (int o = 16; o > 0; o >>= 1) vs += __shfl_xor_sync(~0u, vs, o);
    __syncthreads();
    if ((tid & 31) == 0) sh[tid >> 5] = vs;
    __syncthreads();
    vs = sh[0] + sh[1] + sh[2] + sh[3];
    const float rstd = rsqrtf(vs * (1.0f / (float)D_MODEL) + 1e-5f);
    const int col = tid * 4;
    const float4 gg = *(const float4*)(g + col);
    const float4 bbv = *(const float4*)(bb + col);
    float4 out;
    out.x = (v.x - mean) * rstd * gg.x + bbv.x;
    out.y = (v.y - mean) * rstd * gg.y + bbv.y;
    out.z = (v.z - mean) * rstd * gg.z + bbv.z;
    out.w = (v.w - mean) * rstd * gg.w + bbv.w;
    *(float4*)(y + (size_t)row * D_MODEL + col) = out;
    if (yh != nullptr) {
        uint32_t h0, l0, h1, l1;
        bsplit2(out.x, out.y, h0, l0);
        bsplit2(out.z, out.w, h1, l1);
        size_t o = (size_t)row * D_MODEL + col;
        *(uint32_t*)&yh[o]     = h0;  *(uint32_t*)&yh[o + 2] = h1;
        *(uint32_t*)&yl[o]     = l0;  *(uint32_t*)&yl[o + 2] = l1;
    }
}

// ---------------- orchestration ----------------
extern "C" void kernel_launch(void* const* d_in, const int* in_sizes, int n_in,
                              void* d_out, int out_size)
{
    const float* x_in  = (const float*)d_in[0];
    const float* tau   = (const float*)d_in[1];
    const float* delta = (const float*)d_in[2];
    const float* Wq = (const float*)d_in[4];
    const float* bq = (const float*)d_in[5];
    const float* Wk = (const float*)d_in[6];
    const float* bk = (const float*)d_in[7];
    const float* Wv = (const float*)d_in[8];
    const float* bv = (const float*)d_in[9];
    const float* Wo = (const float*)d_in[10];
    const float* bo = (const float*)d_in[11];
    const float* W1 = (const float*)d_in[12];
    const float* b1 = (const float*)d_in[13];
    const float* W2 = (const float*)d_in[14];
    const float* b2 = (const float*)d_in[15];
    const float* ln1g = (const float*)d_in[16];
    const float* ln1b = (const float*)d_in[17];
    const float* ln2g = (const float*)d_in[18];
    const float* ln2b = (const float*)d_in[19];
    const float* lnfg = (const float*)d_in[20];
    const float* lnfb = (const float*)d_in[21];

    float *gx, *gxb, *go;
    cudaGetSymbolAddress((void**)&gx,  g_x);
    cudaGetSymbolAddress((void**)&gxb, g_xb);
    cudaGetSymbolAddress((void**)&go,  g_o);

    uint16_t *axh, *axl, *axbh, *axbl, *ahh, *ahl, *aath, *aatl;
    cudaGetSymbolAddress((void**)&axh,  s_x_h);
    cudaGetSymbolAddress((void**)&axl,  s_x_l);
    cudaGetSymbolAddress((void**)&axbh, s_xb_h);
    cudaGetSymbolAddress((void**)&axbl, s_xb_l);
    cudaGetSymbolAddress((void**)&ahh,  s_h_h);
    cudaGetSymbolAddress((void**)&ahl,  s_h_l);
    cudaGetSymbolAddress((void**)&aath, s_attn_h);
    cudaGetSymbolAddress((void**)&aatl, s_attn_l);

    uint16_t *wo_h, *wo_l, *w1_h, *w1_l, *w2_h, *w2_l;
    cudaGetSymbolAddress((void**)&wo_h, s_Wo_h);
    cudaGetSymbolAddress((void**)&wo_l, s_Wo_l);
    cudaGetSymbolAddress((void**)&w1_h, s_W1_h);
    cudaGetSymbolAddress((void**)&w1_l, s_W1_l);
    cudaGetSymbolAddress((void**)&w2_h, s_W2_h);
    cudaGetSymbolAddress((void**)&w2_l, s_W2_l);

    cudaFuncSetAttribute(gemm_split,  cudaFuncAttributeMaxDynamicSharedMemorySize, G_SMEM);
    cudaFuncSetAttribute(gemm_qkv,    cudaFuncAttributeMaxDynamicSharedMemorySize, G_SMEM);
    cudaFuncSetAttribute(flash_split, cudaFuncAttributeMaxDynamicSharedMemorySize, F_SMEM);

    // prologue: transpose+split weights, split input
    transp_split<<<dim3(64, 64, 12), 256>>>(Wq, Wk, Wv, Wo, W1, W2);
    split_x<<<ROWS * D_MODEL / 1024, 256>>>(x_in);

    const dim3 gProj(D_MODEL / 128, ROWS / 128);       // (4, 32)
    const dim3 gQKV(D_MODEL / 128, ROWS / 128, 3);     // (4, 32, 3)
    const dim3 gFF1(D_FF / 128, ROWS / 128);           // (16, 32)
    const dim3 gFlash(2 * SEQ / 128, BH);              // (32, 16)
    const dim3 gVT(SEQ / 32, BH);                      // (64, 16)

    for (int l = 0; l < 2; l++) {
        const int wOff   = l * D_MODEL * D_MODEL;
        const int w1Off  = l * D_MODEL * D_FF;
        const size_t bOff  = (size_t)l * D_MODEL;
        const size_t b1Off = (size_t)l * D_FF;

        gemm_qkv<<<gQKV, 256, G_SMEM>>>(bq + bOff, bk + bOff, bv + bOff, wOff);
        vtransp<<<gVT, 256>>>();
        flash_split<<<gFlash, 256, F_SMEM>>>(tau, delta);
        merge_k<<<ROWS * D_MODEL / 512, 256>>>();

        gemm_split<<<gProj, 256, G_SMEM>>>(aath, aatl, wo_h + wOff, wo_l + wOff,
                                           bo + bOff, gx, gx, nullptr, nullptr,
                                           D_MODEL, D_MODEL, 1);
        ln_k<<<ROWS, 128>>>(gx, ln1g + bOff, ln1b + bOff, gxb, axbh, axbl);

        gemm_split<<<gFF1, 256, G_SMEM>>>(axbh, axbl, w1_h + w1Off, w1_l + w1Off,
                                          b1 + b1Off, nullptr, nullptr, ahh, ahl,
                                          D_FF, D_MODEL, 2);
        gemm_split<<<gProj, 256, G_SMEM>>>(ahh, ahl, w2_h + w1Off, w2_l + w1Off,
                                           b2 + bOff, gxb, go, nullptr, nullptr,
                                           D_MODEL, D_FF, 1);
        ln_k<<<ROWS, 128>>>(go, ln2g + bOff, ln2b + bOff, gx, axh, axl);
    }
    ln_k<<<ROWS, 128>>>(gx, lnfg, lnfb, (float*)d_out, nullptr, nullptr);
}

// round 7
// speedup vs baseline: 1.5595x; 1.3050x over previous
#include <cuda_runtime.h>
#include <cuda_fp16.h>
#include <math.h>
#include <stdint.h>

#define D_MODEL 512
#define D_FF 2048
#define BATCH 2
#define SEQ 2048
#define NHEADS 8
#define EDIM 64
#define ROWS (BATCH*SEQ)
#define BH (BATCH*NHEADS)
#define GELU_CF 0.7978845608028654f
#define WSZ  (2*D_MODEL*D_MODEL)
#define W1SZ (2*D_MODEL*D_FF)

// ---------------- f32 scratch ----------------
__device__ float g_x[ROWS*D_MODEL];
__device__ float g_xb[ROWS*D_MODEL];
__device__ float g_o[ROWS*D_MODEL];
__device__ float g_po0[ROWS*D_MODEL];
__device__ float g_po1[ROWS*D_MODEL];
__device__ float g_ml0[BH*SEQ*2];
__device__ float g_ml1[BH*SEQ*2];

// ---------------- fp16 TRANSPOSED weights ([layer][N][K], hi only) ----------------
__device__ uint16_t s_Wq_h[WSZ];
__device__ uint16_t s_Wk_h[WSZ];
__device__ uint16_t s_Wv_h[WSZ];
__device__ uint16_t s_Wo_h[WSZ];
__device__ uint16_t s_W1_h[W1SZ];
__device__ uint16_t s_W2_h[W1SZ];

// ---------------- fp16 activations (A-operands split hi/lo; K/V hi only) --------
__device__ uint16_t s_x_h[ROWS*D_MODEL],    s_x_l[ROWS*D_MODEL];
__device__ uint16_t s_xb_h[ROWS*D_MODEL],   s_xb_l[ROWS*D_MODEL];
__device__ uint16_t s_q_h[ROWS*D_MODEL],    s_q_l[ROWS*D_MODEL];
__device__ uint16_t s_k_h[ROWS*D_MODEL];
__device__ uint16_t s_v_h[ROWS*D_MODEL];
__device__ uint16_t s_vT_h[ROWS*D_MODEL];   // [bh][e][tok]
__device__ uint16_t s_attn_h[ROWS*D_MODEL], s_attn_l[ROWS*D_MODEL];
__device__ uint16_t s_h_h[ROWS*D_FF],       s_h_l[ROWS*D_FF];

// =======================================================================
// helpers
// =======================================================================
__device__ __forceinline__ void hsplit2(float x0, float x1, uint32_t& h, uint32_t& l) {
    __half2 hh = __floats2half2_rn(x0, x1);
    float2 hf = __half22float2(hh);
    __half2 ll = __floats2half2_rn(x0 - hf.x, x1 - hf.y);
    h = *reinterpret_cast<uint32_t*>(&hh);
    l = *reinterpret_cast<uint32_t*>(&ll);
}
__device__ __forceinline__ uint32_t hpack2(float x0, float x1) {
    __half2 hh = __floats2half2_rn(x0, x1);
    return *reinterpret_cast<uint32_t*>(&hh);
}

__device__ __forceinline__ void mma_f16(float* c, const uint32_t* a, const uint32_t* b) {
    asm volatile(
        "mma.sync.aligned.m16n8k16.row.col.f32.f16.f16.f32 "
        "{%0,%1,%2,%3}, {%4,%5,%6,%7}, {%8,%9}, {%0,%1,%2,%3};"
        : "+f"(c[0]), "+f"(c[1]), "+f"(c[2]), "+f"(c[3])
        : "r"(a[0]), "r"(a[1]), "r"(a[2]), "r"(a[3]), "r"(b[0]), "r"(b[1]));
}

__device__ __forceinline__ uint32_t smem_u32(const void* p) {
    uint32_t a;
    asm("{ .reg .u64 t; cvta.to.shared.u64 t, %1; cvt.u32.u64 %0, t; }"
        : "=r"(a) : "l"(p));
    return a;
}

__device__ __forceinline__ void cp16(uint32_t dst, const void* src) {
    asm volatile("cp.async.cg.shared.global [%0], [%1], 16;\n" :: "r"(dst), "l"(src));
}
__device__ __forceinline__ void cp_commit() {
    asm volatile("cp.async.commit_group;\n" ::: "memory");
}
__device__ __forceinline__ void cp_wait1() {
    asm volatile("cp.async.wait_group 1;\n" ::: "memory");
}
__device__ __forceinline__ void cp_wait0() {
    asm volatile("cp.async.wait_group 0;\n" ::: "memory");
}

// =======================================================================
// prologue: transpose weights -> fp16 hi;  split input x
// =======================================================================
__global__ __launch_bounds__(256) void transp_split(
    const float* __restrict__ Wq, const float* __restrict__ Wk,
    const float* __restrict__ Wv, const float* __restrict__ Wo,
    const float* __restrict__ W1, const float* __restrict__ W2)
{
    const int w = blockIdx.z >> 1, layer = blockIdx.z & 1;
    const float* src; uint16_t* dh; int K, N;
    switch (w) {
        case 0: src = Wq; dh = s_Wq_h; K = 512;  N = 512;  break;
        case 1: src = Wk; dh = s_Wk_h; K = 512;  N = 512;  break;
        case 2: src = Wv; dh = s_Wv_h; K = 512;  N = 512;  break;
        case 3: src = Wo; dh = s_Wo_h; K = 512;  N = 512;  break;
        case 4: src = W1; dh = s_W1_h; K = 512;  N = 2048; break;
        default: src = W2; dh = s_W2_h; K = 2048; N = 512; break;
    }
    const int k0 = blockIdx.x * 32, n0 = blockIdx.y * 32;
    if (k0 >= K || n0 >= N) return;
    src += (size_t)layer * K * N;
    dh  += (size_t)layer * K * N;

    __shared__ float t[32][33];
    const int tid = threadIdx.x;
    const int tx = tid & 31, ty = tid >> 5;
    #pragma unroll
    for (int i = 0; i < 4; i++) {
        int k = ty + i * 8;
        t[k][tx] = src[(size_t)(k0 + k) * N + n0 + tx];
    }
    __syncthreads();
    const int n = tid >> 3, kq = tid & 7;
    float a0 = t[kq*4+0][n], a1 = t[kq*4+1][n], a2 = t[kq*4+2][n], a3 = t[kq*4+3][n];
    size_t o = (size_t)(n0 + n) * K + k0 + kq * 4;
    *(uint32_t*)&dh[o]     = hpack2(a0, a1);
    *(uint32_t*)&dh[o + 2] = hpack2(a2, a3);
}

__global__ __launch_bounds__(256) void split_x(const float* __restrict__ x)
{
    int idx = (blockIdx.x * 256 + threadIdx.x) * 4;
    float4 v = *(const float4*)(x + idx);
    *(float4*)(g_x + idx) = v;
    uint32_t h0, l0, h1, l1;
    hsplit2(v.x, v.y, h0, l0);
    hsplit2(v.z, v.w, h1, l1);
    *(uint32_t*)&s_x_h[idx]     = h0;  *(uint32_t*)&s_x_h[idx + 2] = h1;
    *(uint32_t*)&s_x_l[idx]     = l0;  *(uint32_t*)&s_x_l[idx + 2] = l1;
}

// V transpose: s_v_h [tok][h*64+e] -> s_vT_h [bh][e][tok]
__global__ __launch_bounds__(256) void vtransp()
{
    __shared__ uint16_t tt[32][66];
    const int bh = blockIdx.y;
    const int b = bh >> 3, h = bh & 7;
    const int tok0 = blockIdx.x * 32;
    const int tid = threadIdx.x;
    #pragma unroll
    for (int i = 0; i < 4; i++) {
        int idx = tid + i * 256;           // 32 toks x 32 u32
        int r = idx >> 5, c = idx & 31;
        uint32_t v = *(const uint32_t*)&s_v_h[(size_t)(b * SEQ + tok0 + r) * D_MODEL + h * 64 + c * 2];
        *(uint32_t*)&tt[r][c * 2] = v;
    }
    __syncthreads();
    #pragma unroll
    for (int i = 0; i < 4; i++) {
        int idx = tid + i * 256;           // 64 e x 16 u32
        int e = idx >> 4, t2 = idx & 15;
        uint32_t v = (uint32_t)tt[t2 * 2][e] | ((uint32_t)tt[t2 * 2 + 1][e] << 16);
        *(uint32_t*)&s_vT_h[((size_t)bh * EDIM + e) * SEQ + tok0 + t2 * 2] = v;
    }
}

// =======================================================================
// GEMM: A split fp16 [M][K] hi/lo, B = fp16 weights [N][K] hi only.
// C = Ah.Bh + Al.Bh. Tile 128x128, BK=32, 256 thr, cp.async double-buffered.
// Stage: Ah(10240) Al(10240) Bh(10240) = 30720
// =======================================================================
#define A_PITCH 40
#define G_STAGE 30720
#define G_SMEM (2*G_STAGE)

// epi: 0 = bias -> fp16 out; 1 = bias + add -> f32 out; 2 = bias + gelu -> fp16 out
__device__ __forceinline__ void gemm_body(
    const uint16_t* __restrict__ Ah, const uint16_t* __restrict__ Al,
    const uint16_t* __restrict__ Bh,
    const float* __restrict__ bias, const float* __restrict__ add,
    float* __restrict__ Cf, uint16_t* __restrict__ Ch, uint16_t* __restrict__ Cl,
    int N, int K, int epi, int bm, int bn, char* sm)
{
    const int tid = threadIdx.x;
    const int wid = tid >> 5;
    const int lane = tid & 31;
    const int wm = wid & 1;
    const int wn = wid >> 1;
    const int fr = lane >> 2;
    const int fkc = (lane & 3) * 2;
    const uint32_t sb = smem_u32(sm);

    float acc[4][4][4];
    #pragma unroll
    for (int tm = 0; tm < 4; tm++)
        #pragma unroll
        for (int tn = 0; tn < 4; tn++)
            #pragma unroll
            for (int i = 0; i < 4; i++) acc[tm][tn][i] = 0.f;

    const int nChunks = K >> 5;

    auto issue = [&](int st, int kt) {
        uint32_t base = sb + st * G_STAGE;
        #pragma unroll
        for (int t = 0; t < 2; t++) {
            int idx = tid + t * 256;
            int row = idx >> 2, c4 = idx & 3;
            size_t ga = (size_t)(bm + row) * K + kt + c4 * 8;
            cp16(base + row * 80 + c4 * 16, Ah + ga);
            cp16(base + 10240 + row * 80 + c4 * 16, Al + ga);
            size_t gb = (size_t)(bn + row) * K + kt + c4 * 8;
            cp16(base + 20480 + row * 80 + c4 * 16, Bh + gb);
        }
        cp_commit();
    };

    issue(0, 0);

    for (int chunk = 0; chunk < nChunks; chunk++) {
        if (chunk + 1 < nChunks) {
            issue((chunk + 1) & 1, (chunk + 1) << 5);
            cp_wait1();
        } else {
            cp_wait0();
        }
        __syncthreads();

        const char* stg = sm + (chunk & 1) * G_STAGE;
        const uint16_t* sAh = (const uint16_t*)(stg);
        const uint16_t* sAl = (const uint16_t*)(stg + 10240);
        const uint16_t* sBh = (const uint16_t*)(stg + 20480);

        #pragma unroll
        for (int ks = 0; ks < 2; ks++) {
            const int K0 = ks * 16;
            uint32_t ah[4][4], al[4][4];
            #pragma unroll
            for (int tm = 0; tm < 4; tm++) {
                int base = (wm * 64 + tm * 16 + fr) * A_PITCH + K0 + fkc;
                ah[tm][0] = *(const uint32_t*)&sAh[base];
                ah[tm][1] = *(const uint32_t*)&sAh[base + 8 * A_PITCH];
                ah[tm][2] = *(const uint32_t*)&sAh[base + 8];
                ah[tm][3] = *(const uint32_t*)&sAh[base + 8 * A_PITCH + 8];
                al[tm][0] = *(const uint32_t*)&sAl[base];
                al[tm][1] = *(const uint32_t*)&sAl[base + 8 * A_PITCH];
                al[tm][2] = *(const uint32_t*)&sAl[base + 8];
                al[tm][3] = *(const uint32_t*)&sAl[base + 8 * A_PITCH + 8];
            }
            uint32_t bh[4][2];
            #pragma unroll
            for (int tn = 0; tn < 4; tn++) {
                int nb = (wn * 32 + tn * 8 + fr) * A_PITCH + K0 + fkc;
                bh[tn][0] = *(const uint32_t*)&sBh[nb];
                bh[tn][1] = *(const uint32_t*)&sBh[nb + 8];
            }
            #pragma unroll
            for (int tm = 0; tm < 4; tm++)
                #pragma unroll
                for (int tn = 0; tn < 4; tn++)
                    mma_f16(acc[tm][tn], ah[tm], bh[tn]);
            #pragma unroll
            for (int tm = 0; tm < 4; tm++)
                #pragma unroll
                for (int tn = 0; tn < 4; tn++)
                    mma_f16(acc[tm][tn], al[tm], bh[tn]);
        }
        __syncthreads();
    }

    #pragma unroll
    for (int tm = 0; tm < 4; tm++) {
        #pragma unroll
        for (int tn = 0; tn < 4; tn++) {
            int row0 = bm + wm * 64 + tm * 16 + fr;
            int col = bn + wn * 32 + tn * 8 + fkc;
            float b0 = bias[col], b1 = bias[col + 1];
            #pragma unroll
            for (int half = 0; half < 2; half++) {
                int row = row0 + half * 8;
                float v0 = acc[tm][tn][half * 2 + 0] + b0;
                float v1 = acc[tm][tn][half * 2 + 1] + b1;
                if (epi == 1) {
                    const float* ap = add + (size_t)row * N + col;
                    v0 += ap[0]; v1 += ap[1];
                    *(float2*)(Cf + (size_t)row * N + col) = make_float2(v0, v1);
                } else {
                    if (epi == 2) {
                        float u = v0;
                        v0 = 0.5f * u * (1.0f + tanhf(GELU_CF * (u + 0.044715f * u * u * u)));
                        u = v1;
                        v1 = 0.5f * u * (1.0f + tanhf(GELU_CF * (u + 0.044715f * u * u * u)));
                    }
                    uint32_t h, l;
                    hsplit2(v0, v1, h, l);
                    *(uint32_t*)&Ch[(size_t)row * N + col] = h;
                    if (Cl) *(uint32_t*)&Cl[(size_t)row * N + col] = l;
                }
            }
        }
    }
}

__global__ __launch_bounds__(256, 2) void gemm_split(
    const uint16_t* __restrict__ Ah, const uint16_t* __restrict__ Al,
    const uint16_t* __restrict__ Bh,
    const float* __restrict__ bias, const float* __restrict__ add,
    float* __restrict__ Cf, uint16_t* __restrict__ Ch, uint16_t* __restrict__ Cl,
    int N, int K, int epi)
{
    extern __shared__ char sm[];
    gemm_body(Ah, Al, Bh, bias, add, Cf, Ch, Cl, N, K, epi,
              blockIdx.y * 128, blockIdx.x * 128, sm);
}

__global__ __launch_bounds__(256, 2) void gemm_qkv(
    const float* __restrict__ bq, const float* __restrict__ bk,
    const float* __restrict__ bv, int lw)
{
    extern __shared__ char sm[];
    const int z = blockIdx.z;
    const uint16_t* Bh;
    const float* bias;
    uint16_t *Ch, *Cl;
    if (z == 0)      { Bh = s_Wq_h + lw; bias = bq; Ch = s_q_h; Cl = s_q_l; }
    else if (z == 1) { Bh = s_Wk_h + lw; bias = bk; Ch = s_k_h; Cl = nullptr; }
    else             { Bh = s_Wv_h + lw; bias = bv; Ch = s_v_h; Cl = nullptr; }
    gemm_body(s_x_h, s_x_l, Bh, bias, nullptr, nullptr, Ch, Cl,
              D_MODEL, D_MODEL, 0, blockIdx.y * 128, blockIdx.x * 128, sm);
}

// =======================================================================
// Flash attention, 2-way split-KV. Q split hi/lo; K, V^T fp16 hi only.
// Stage: Kh(9216) VTh(9216) = 18432; 2 stages.
// =======================================================================
#define KP 72
#define F_STAGE 18432
#define F_SMEM (2*F_STAGE)

__global__ __launch_bounds__(256, 2) void flash_split(
    const float* __restrict__ tau, const float* __restrict__ delta)
{
    extern __shared__ char sm[];
    const uint32_t sb = smem_u32(sm);
    const int tid = threadIdx.x;
    const int wid = tid >> 5;
    const int lane = tid & 31;
    const int fr = lane >> 2;
    const int fkc = (lane & 3) * 2;

    const int nLt = gridDim.x >> 1;
    const int lt = nLt - 1 - (blockIdx.x >> 1);
    const int z = blockIdx.x & 1;
    const int bh = blockIdx.y;
    const int b = bh >> 3, h = bh & 7;
    const int qrow0 = lt * 128;
    const int rA = qrow0 + wid * 16 + fr;
    const int rB = rA + 8;

    uint32_t qh[4][4], ql[4][4];
    #pragma unroll
    for (int ks = 0; ks < 4; ks++) {
        int e0 = ks * 16 + fkc;
        size_t oA = (size_t)(b * SEQ + rA) * D_MODEL + h * EDIM + e0;
        size_t oB = (size_t)(b * SEQ + rB) * D_MODEL + h * EDIM + e0;
        qh[ks][0] = *(const uint32_t*)&s_q_h[oA];
        qh[ks][1] = *(const uint32_t*)&s_q_h[oB];
        qh[ks][2] = *(const uint32_t*)&s_q_h[oA + 8];
        qh[ks][3] = *(const uint32_t*)&s_q_h[oB + 8];
        ql[ks][0] = *(const uint32_t*)&s_q_l[oA];
        ql[ks][1] = *(const uint32_t*)&s_q_l[oB];
        ql[ks][2] = *(const uint32_t*)&s_q_l[oA + 8];
        ql[ks][3] = *(const uint32_t*)&s_q_l[oB + 8];
    }

    float oacc[8][4];
    #pragma unroll
    for (int t = 0; t < 8; t++)
        #pragma unroll
        for (int i = 0; i < 4; i++) oacc[t][i] = 0.f;
    float m0 = -3.0e38f, m1 = -3.0e38f;
    float l0 = 0.f, l1 = 0.f;
    const float sct = 0.125f * __ldg(&tau[b]);

    const int stStart = z * (lt + 1);
    const int nTiles = lt + 1;

    auto issue = [&](int stage, int key_base) {
        uint32_t base = sb + stage * F_STAGE;
        {
            int idx = tid;                      // 64 rows x 8 cp16, 512 total over 2 arrays
            int row = idx >> 2, c4 = idx & 3;
            size_t gk = (size_t)(b * SEQ + key_base + row) * D_MODEL + h * EDIM + c4 * 16;
            uint32_t dk = base + row * 144 + c4 * 32;
            cp16(dk, s_k_h + gk);
            cp16(dk + 16, s_k_h + gk + 8);
            size_t gv = ((size_t)bh * EDIM + row) * SEQ + key_base + c4 * 16;
            uint32_t dv = base + 9216 + row * 144 + c4 * 32;
            cp16(dv, s_vT_h + gv);
            cp16(dv + 16, s_vT_h + gv + 8);
        }
        cp_commit();
    };

    issue(0, stStart * 64);

    for (int it = 0; it < nTiles; it++) {
        const int key_base = (stStart + it) * 64;
        if (it + 1 < nTiles) {
            issue((it + 1) & 1, key_base + 64);
            cp_wait1();
        } else {
            cp_wait0();
        }
        __syncthreads();

        const char* stg = sm + (it & 1) * F_STAGE;
        const uint16_t* sKh  = (const uint16_t*)(stg);
        const uint16_t* sVTh = (const uint16_t*)(stg + 9216);

        // ---- S = Q K^T ----
        float s[8][4];
        #pragma unroll
        for (int t = 0; t < 8; t++)
            #pragma unroll
            for (int i = 0; i < 4; i++) s[t][i] = 0.f;

        #pragma unroll
        for (int ks = 0; ks < 4; ks++) {
            const int K0 = ks * 16;
            #pragma unroll
            for (int tn = 0; tn < 8; tn++) {
                int base = (tn * 8 + fr) * KP + K0 + fkc;
                uint32_t bhh[2];
                bhh[0] = *(const uint32_t*)&sKh[base];
                bhh[1] = *(const uint32_t*)&sKh[base + 8];
                mma_f16(s[tn], qh[ks], bhh);
                mma_f16(s[tn], ql[ks], bhh);
            }
        }

        // ---- scale + bias + mask ----
        const bool masked = (key_base + 63) > qrow0;
        #pragma unroll
        for (int tn = 0; tn < 8; tn++) {
            int key = key_base + tn * 8 + fkc;
            float2 dd = *(const float2*)(delta + b * SEQ + key);
            float d0 = 0.125f * dd.x, d1 = 0.125f * dd.y;
            s[tn][0] = fmaf(s[tn][0], sct, d0);
            s[tn][1] = fmaf(s[tn][1], sct, d1);
            s[tn][2] = fmaf(s[tn][2], sct, d0);
            s[tn][3] = fmaf(s[tn][3], sct, d1);
            if (masked) {
                if (key     > rA) s[tn][0] = -1e30f;
                if (key + 1 > rA) s[tn][1] = -1e30f;
                if (key     > rB) s[tn][2] = -1e30f;
                if (key + 1 > rB) s[tn][3] = -1e30f;
            }
        }

        // ---- online softmax ----
        float r0 = -3.0e38f, r1 = -3.0e38f;
        #pragma unroll
        for (int tn = 0; tn < 8; tn++) {
            r0 = fmaxf(r0, fmaxf(s[tn][0], s[tn][1]));
            r1 = fmaxf(r1, fmaxf(s[tn][2], s[tn][3]));
        }
        r0 = fmaxf(r0, __shfl_xor_sync(~0u, r0, 1));
        r0 = fmaxf(r0, __shfl_xor_sync(~0u, r0, 2));
        r1 = fmaxf(r1, __shfl_xor_sync(~0u, r1, 1));
        r1 = fmaxf(r1, __shfl_xor_sync(~0u, r1, 2));
        float mn0 = fmaxf(m0, r0), mn1 = fmaxf(m1, r1);
        float sc0 = __expf(m0 - mn0), sc1 = __expf(m1 - mn1);
        float sum0 = 0.f, sum1 = 0.f;
        #pragma unroll
        for (int tn = 0; tn < 8; tn++) {
            s[tn][0] = __expf(s[tn][0] - mn0); sum0 += s[tn][0];
            s[tn][1] = __expf(s[tn][1] - mn0); sum0 += s[tn][1];
            s[tn][2] = __expf(s[tn][2] - mn1); sum1 += s[tn][2];
            s[tn][3] = __expf(s[tn][3] - mn1); sum1 += s[tn][3];
        }
        sum0 += __shfl_xor_sync(~0u, sum0, 1);
        sum0 += __shfl_xor_sync(~0u, sum0, 2);
        sum1 += __shfl_xor_sync(~0u, sum1, 1);
        sum1 += __shfl_xor_sync(~0u, sum1, 2);
        l0 = l0 * sc0 + sum0; m0 = mn0;
        l1 = l1 * sc1 + sum1; m1 = mn1;
        #pragma unroll
        for (int t = 0; t < 8; t++) {
            oacc[t][0] *= sc0; oacc[t][1] *= sc0;
            oacc[t][2] *= sc1; oacc[t][3] *= sc1;
        }

        // ---- O += P V  (P split hi/lo; V single) ----
        #pragma unroll
        for (int kc = 0; kc < 4; kc++) {
            uint32_t ah[4], al[4];
            hsplit2(s[2*kc][0],   s[2*kc][1],   ah[0], al[0]);
            hsplit2(s[2*kc][2],   s[2*kc][3],   ah[1], al[1]);
            hsplit2(s[2*kc+1][0], s[2*kc+1][1], ah[2], al[2]);
            hsplit2(s[2*kc+1][2], s[2*kc+1][3], ah[3], al[3]);
            #pragma unroll
            for (int tn2 = 0; tn2 < 8; tn2++) {
                int vb = (tn2 * 8 + fr) * KP + kc * 16 + fkc;
                uint32_t bvh[2];
                bvh[0] = *(const uint32_t*)&sVTh[vb];
                bvh[1] = *(const uint32_t*)&sVTh[vb + 8];
                mma_f16(oacc[tn2], ah, bvh);
                mma_f16(oacc[tn2], al, bvh);
            }
        }
        __syncthreads();
    }

    // ---- write partials (unnormalized O, plus m/l) ----
    float* po = z ? g_po1 : g_po0;
    float* ml = z ? g_ml1 : g_ml0;
    #pragma unroll
    for (int tn2 = 0; tn2 < 8; tn2++) {
        int col = h * EDIM + tn2 * 8 + fkc;
        *(float2*)&po[(size_t)(b * SEQ + rA) * D_MODEL + col] = make_float2(oacc[tn2][0], oacc[tn2][1]);
        *(float2*)&po[(size_t)(b * SEQ + rB) * D_MODEL + col] = make_float2(oacc[tn2][2], oacc[tn2][3]);
    }
    if ((lane & 3) == 0) {
        *(float2*)&ml[(size_t)(bh * SEQ + rA) * 2] = make_float2(m0, l0);
        *(float2*)&ml[(size_t)(bh * SEQ + rB) * 2] = make_float2(m1, l1);
    }
}

// merge split-KV partials -> split attn output
__global__ __launch_bounds__(256) void merge_k()
{
    const int idx2 = (blockIdx.x * 256 + threadIdx.x) * 2;
    const int r = idx2 >> 9;
    const int d = idx2 & 511;
    const int bh = ((r >> 11) << 3) | (d >> 6);
    const int srow = r & (SEQ - 1);
    float2 ml0 = *(float2*)&g_ml0[(size_t)(bh * SEQ + srow) * 2];
    float2 ml1 = *(float2*)&g_ml1[(size_t)(bh * SEQ + srow) * 2];
    float M = fmaxf(ml0.x, ml1.x);
    float w0 = __expf(ml0.x - M), w1 = __expf(ml1.x - M);
    float inv = 1.0f / (ml0.y * w0 + ml1.y * w1);
    float2 p0 = *(float2*)&g_po0[idx2];
    float2 p1 = *(float2*)&g_po1[idx2];
    float v0 = (p0.x * w0 + p1.x * w1) * inv;
    float v1 = (p0.y * w0 + p1.y * w1) * inv;
    uint32_t hh, ll;
    hsplit2(v0, v1, hh, ll);
    *(uint32_t*)&s_attn_h[idx2] = hh;
    *(uint32_t*)&s_attn_l[idx2] = ll;
}

// ---------------- LayerNorm (+ optional split outputs) ----------------
__global__ __launch_bounds__(128) void ln_k(
    const float* __restrict__ x, const float* __restrict__ g,
    const float* __restrict__ bb, float* __restrict__ y,
    uint16_t* __restrict__ yh, uint16_t* __restrict__ yl)
{
    const int row = blockIdx.x;
    const float* p = x + (size_t)row * D_MODEL;
    const int tid = threadIdx.x;
    float4 v = *(const float4*)(p + tid * 4);
    float s = v.x + v.y + v.z + v.w;
    __shared__ float sh[4];
    #pragma unroll
    for (int o = 16; o > 0; o >>= 1) s += __shfl_xor_sync(~0u, s, o);
    if ((tid & 31) == 0) sh[tid >> 5] = s;
    __syncthreads();
    s = sh[0] + sh[1] + sh[2] + sh[3];
    const float mean = s * (1.0f / (float)D_MODEL);
    float vs = (v.x - mean) * (v.x - mean) + (v.y - mean) * (v.y - mean)
             + (v.z - mean) * (v.z - mean) + (v.w - mean) * (v.w - mean);
    #pragma unroll
    for (int o = 16; o > 0; o >>= 1) vs += __shfl_xor_sync(~0u, vs, o);
    __syncthreads();
    if ((tid & 31) == 0) sh[tid >> 5] = vs;
    __syncthreads();
    vs = sh[0] + sh[1] + sh[2] + sh[3];
    const float rstd = rsqrtf(vs * (1.0f / (float)D_MODEL) + 1e-5f);
    const int col = tid * 4;
    const float4 gg = *(const float4*)(g + col);
    const float4 bbv = *(const float4*)(bb + col);
    float4 out;
    out.x = (v.x - mean) * rstd * gg.x + bbv.x;
    out.y = (v.y - mean) * rstd * gg.y + bbv.y;
    out.z = (v.z - mean) * rstd * gg.z + bbv.z;
    out.w = (v.w - mean) * rstd * gg.w + bbv.w;
    *(float4*)(y + (size_t)row * D_MODEL + col) = out;
    if (yh != nullptr) {
        uint32_t h0, l0, h1, l1;
        hsplit2(out.x, out.y, h0, l0);
        hsplit2(out.z, out.w, h1, l1);
        size_t o = (size_t)row * D_MODEL + col;
        *(uint32_t*)&yh[o]     = h0;  *(uint32_t*)&yh[o + 2] = h1;
        *(uint32_t*)&yl[o]     = l0;  *(uint32_t*)&yl[o + 2] = l1;
    }
}

// ---------------- orchestration ----------------
extern "C" void kernel_launch(void* const* d_in, const int* in_sizes, int n_in,
                              void* d_out, int out_size)
{
    const float* x_in  = (const float*)d_in[0];
    const float* tau   = (const float*)d_in[1];
    const float* delta = (const float*)d_in[2];
    const float* Wq = (const float*)d_in[4];
    const float* bq = (const float*)d_in[5];
    const float* Wk = (const float*)d_in[6];
    const float* bk = (const float*)d_in[7];
    const float* Wv = (const float*)d_in[8];
    const float* bv = (const float*)d_in[9];
    const float* Wo = (const float*)d_in[10];
    const float* bo = (const float*)d_in[11];
    const float* W1 = (const float*)d_in[12];
    const float* b1 = (const float*)d_in[13];
    const float* W2 = (const float*)d_in[14];
    const float* b2 = (const float*)d_in[15];
    const float* ln1g = (const float*)d_in[16];
    const float* ln1b = (const float*)d_in[17];
    const float* ln2g = (const float*)d_in[18];
    const float* ln2b = (const float*)d_in[19];
    const float* lnfg = (const float*)d_in[20];
    const float* lnfb = (const float*)d_in[21];

    float *gx, *gxb, *go;
    cudaGetSymbolAddress((void**)&gx,  g_x);
    cudaGetSymbolAddress((void**)&gxb, g_xb);
    cudaGetSymbolAddress((void**)&go,  g_o);

    uint16_t *axh, *axl, *axbh, *axbl, *ahh, *ahl, *aath, *aatl;
    cudaGetSymbolAddress((void**)&axh,  s_x_h);
    cudaGetSymbolAddress((void**)&axl,  s_x_l);
    cudaGetSymbolAddress((void**)&axbh, s_xb_h);
    cudaGetSymbolAddress((void**)&axbl, s_xb_l);
    cudaGetSymbolAddress((void**)&ahh,  s_h_h);
    cudaGetSymbolAddress((void**)&ahl,  s_h_l);
    cudaGetSymbolAddress((void**)&aath, s_attn_h);
    cudaGetSymbolAddress((void**)&aatl, s_attn_l);

    uint16_t *wo_h, *w1_h, *w2_h;
    cudaGetSymbolAddress((void**)&wo_h, s_Wo_h);
    cudaGetSymbolAddress((void**)&w1_h, s_W1_h);
    cudaGetSymbolAddress((void**)&w2_h, s_W2_h);

    cudaFuncSetAttribute(gemm_split,  cudaFuncAttributeMaxDynamicSharedMemorySize, G_SMEM);
    cudaFuncSetAttribute(gemm_qkv,    cudaFuncAttributeMaxDynamicSharedMemorySize, G_SMEM);
    cudaFuncSetAttribute(flash_split, cudaFuncAttributeMaxDynamicSharedMemorySize, F_SMEM);

    // prologue: transpose+round weights, split input
    transp_split<<<dim3(64, 64, 12), 256>>>(Wq, Wk, Wv, Wo, W1, W2);
    split_x<<<ROWS * D_MODEL / 1024, 256>>>(x_in);

    const dim3 gProj(D_MODEL / 128, ROWS / 128);       // (4, 32)
    const dim3 gQKV(D_MODEL / 128, ROWS / 128, 3);     // (4, 32, 3)
    const dim3 gFF1(D_FF / 128, ROWS / 128);           // (16, 32)
    const dim3 gFlash(2 * SEQ / 128, BH);              // (32, 16)
    const dim3 gVT(SEQ / 32, BH);                      // (64, 16)

    for (int l = 0; l < 2; l++) {
        const int wOff   = l * D_MODEL * D_MODEL;
        const int w1Off  = l * D_MODEL * D_FF;
        const size_t bOff  = (size_t)l * D_MODEL;
        const size_t b1Off = (size_t)l * D_FF;

        gemm_qkv<<<gQKV, 256, G_SMEM>>>(bq + bOff, bk + bOff, bv + bOff, wOff);
        vtransp<<<gVT, 256>>>();
        flash_split<<<gFlash, 256, F_SMEM>>>(tau, delta);
        merge_k<<<ROWS * D_MODEL / 512, 256>>>();

        gemm_split<<<gProj, 256, G_SMEM>>>(aath, aatl, wo_h + wOff,
                                           bo + bOff, gx, gx, nullptr, nullptr,
                                           D_MODEL, D_MODEL, 1);
        ln_k<<<ROWS, 128>>>(gx, ln1g + bOff, ln1b + bOff, gxb, axbh, axbl);

        gemm_split<<<gFF1, 256, G_SMEM>>>(axbh, axbl, w1_h + w1Off,
                                          b1 + b1Off, nullptr, nullptr, ahh, ahl,
                                          D_FF, D_MODEL, 2);
        gemm_split<<<gProj, 256, G_SMEM>>>(ahh, ahl, w2_h + w1Off,
                                           b2 + bOff, gxb, go, nullptr, nullptr,
                                           D_MODEL, D_FF, 1);
        ln_k<<<ROWS, 128>>>(go, ln2g + bOff, ln2b + bOff, gx, axh, axl);
    }
    ln_k<<<ROWS, 128>>>(gx, lnfg, lnfb, (float*)d_out, nullptr, nullptr);
}

// round 8
// speedup vs baseline: 2.2654x; 1.4526x over previous
#include <cuda_runtime.h>
#include <cuda_fp16.h>
#include <math.h>
#include <stdint.h>

#define D_MODEL 512
#define D_FF 2048
#define BATCH 2
#define SEQ 2048
#define NHEADS 8
#define EDIM 64
#define ROWS (BATCH*SEQ)
#define BH (BATCH*NHEADS)
#define GELU_CF 0.7978845608028654f
#define WSZ  (2*D_MODEL*D_MODEL)
#define W1SZ (2*D_MODEL*D_FF)

// ---------------- f32 scratch ----------------
__device__ float g_x[ROWS*D_MODEL];
__device__ float g_xb[ROWS*D_MODEL];
__device__ float g_o[ROWS*D_MODEL];
__device__ float g_po0[ROWS*D_MODEL];
__device__ float g_po1[ROWS*D_MODEL];
__device__ float g_ml0[BH*SEQ*2];
__device__ float g_ml1[BH*SEQ*2];

// ---------------- fp16 TRANSPOSED weights ([layer][N][K]) ----------------
__device__ uint16_t s_Wq_h[WSZ];
__device__ uint16_t s_Wk_h[WSZ];
__device__ uint16_t s_Wv_h[WSZ];
__device__ uint16_t s_Wo_h[WSZ];
__device__ uint16_t s_W1_h[W1SZ];
__device__ uint16_t s_W2_h[W1SZ];

// ---------------- fp16 activations ----------------
__device__ uint16_t s_x_h[ROWS*D_MODEL];
__device__ uint16_t s_xb_h[ROWS*D_MODEL];
__device__ uint16_t s_q_h[ROWS*D_MODEL];
__device__ uint16_t s_k_h[ROWS*D_MODEL];
__device__ uint16_t s_v_h[ROWS*D_MODEL];
__device__ uint16_t s_vT_h[ROWS*D_MODEL];   // [bh][e][tok]
__device__ uint16_t s_attn_h[ROWS*D_MODEL];
__device__ uint16_t s_h_h[ROWS*D_FF];

// =======================================================================
// helpers
// =======================================================================
__device__ __forceinline__ uint32_t hpack2(float x0, float x1) {
    __half2 hh = __floats2half2_rn(x0, x1);
    return *reinterpret_cast<uint32_t*>(&hh);
}

__device__ __forceinline__ void mma_f16(float* c, const uint32_t* a, const uint32_t* b) {
    asm volatile(
        "mma.sync.aligned.m16n8k16.row.col.f32.f16.f16.f32 "
        "{%0,%1,%2,%3}, {%4,%5,%6,%7}, {%8,%9}, {%0,%1,%2,%3};"
        : "+f"(c[0]), "+f"(c[1]), "+f"(c[2]), "+f"(c[3])
        : "r"(a[0]), "r"(a[1]), "r"(a[2]), "r"(a[3]), "r"(b[0]), "r"(b[1]));
}

__device__ __forceinline__ uint32_t smem_u32(const void* p) {
    uint32_t a;
    asm("{ .reg .u64 t; cvta.to.shared.u64 t, %1; cvt.u32.u64 %0, t; }"
        : "=r"(a) : "l"(p));
    return a;
}

__device__ __forceinline__ void cp16(uint32_t dst, const void* src) {
    asm volatile("cp.async.cg.shared.global [%0], [%1], 16;\n" :: "r"(dst), "l"(src));
}
__device__ __forceinline__ void cp_commit() {
    asm volatile("cp.async.commit_group;\n" ::: "memory");
}
__device__ __forceinline__ void cp_wait2() {
    asm volatile("cp.async.wait_group 2;\n" ::: "memory");
}
__device__ __forceinline__ void cp_wait1() {
    asm volatile("cp.async.wait_group 1;\n" ::: "memory");
}
__device__ __forceinline__ void cp_wait0() {
    asm volatile("cp.async.wait_group 0;\n" ::: "memory");
}

// =======================================================================
// prologue
// =======================================================================
__global__ __launch_bounds__(256) void transp_split(
    const float* __restrict__ Wq, const float* __restrict__ Wk,
    const float* __restrict__ Wv, const float* __restrict__ Wo,
    const float* __restrict__ W1, const float* __restrict__ W2)
{
    const int w = blockIdx.z >> 1, layer = blockIdx.z & 1;
    const float* src; uint16_t* dh; int K, N;
    switch (w) {
        case 0: src = Wq; dh = s_Wq_h; K = 512;  N = 512;  break;
        case 1: src = Wk; dh = s_Wk_h; K = 512;  N = 512;  break;
        case 2: src = Wv; dh = s_Wv_h; K = 512;  N = 512;  break;
        case 3: src = Wo; dh = s_Wo_h; K = 512;  N = 512;  break;
        case 4: src = W1; dh = s_W1_h; K = 512;  N = 2048; break;
        default: src = W2; dh = s_W2_h; K = 2048; N = 512; break;
    }
    const int k0 = blockIdx.x * 32, n0 = blockIdx.y * 32;
    if (k0 >= K || n0 >= N) return;
    src += (size_t)layer * K * N;
    dh  += (size_t)layer * K * N;

    __shared__ float t[32][33];
    const int tid = threadIdx.x;
    const int tx = tid & 31, ty = tid >> 5;
    #pragma unroll
    for (int i = 0; i < 4; i++) {
        int k = ty + i * 8;
        t[k][tx] = src[(size_t)(k0 + k) * N + n0 + tx];
    }
    __syncthreads();
    const int n = tid >> 3, kq = tid & 7;
    float a0 = t[kq*4+0][n], a1 = t[kq*4+1][n], a2 = t[kq*4+2][n], a3 = t[kq*4+3][n];
    size_t o = (size_t)(n0 + n) * K + k0 + kq * 4;
    *(uint32_t*)&dh[o]     = hpack2(a0, a1);
    *(uint32_t*)&dh[o + 2] = hpack2(a2, a3);
}

__global__ __launch_bounds__(256) void split_x(const float* __restrict__ x)
{
    int idx = (blockIdx.x * 256 + threadIdx.x) * 4;
    float4 v = *(const float4*)(x + idx);
    *(float4*)(g_x + idx) = v;
    *(uint32_t*)&s_x_h[idx]     = hpack2(v.x, v.y);
    *(uint32_t*)&s_x_h[idx + 2] = hpack2(v.z, v.w);
}

// V transpose: s_v_h [tok][h*64+e] -> s_vT_h [bh][e][tok]
__global__ __launch_bounds__(256) void vtransp()
{
    __shared__ uint16_t tt[32][66];
    const int bh = blockIdx.y;
    const int b = bh >> 3, h = bh & 7;
    const int tok0 = blockIdx.x * 32;
    const int tid = threadIdx.x;
    #pragma unroll
    for (int i = 0; i < 4; i++) {
        int idx = tid + i * 256;
        int r = idx >> 5, c = idx & 31;
        uint32_t v = *(const uint32_t*)&s_v_h[(size_t)(b * SEQ + tok0 + r) * D_MODEL + h * 64 + c * 2];
        *(uint32_t*)&tt[r][c * 2] = v;
    }
    __syncthreads();
    #pragma unroll
    for (int i = 0; i < 4; i++) {
        int idx = tid + i * 256;
        int e = idx >> 4, t2 = idx & 15;
        uint32_t v = (uint32_t)tt[t2 * 2][e] | ((uint32_t)tt[t2 * 2 + 1][e] << 16);
        *(uint32_t*)&s_vT_h[((size_t)bh * EDIM + e) * SEQ + tok0 + t2 * 2] = v;
    }
}

// =======================================================================
// GEMM: pure fp16. A [M][K], B (transposed weights) [N][K].
// Tile 128x128, BK=32, 256 thr. 3-stage cp.async pipeline.
// Stage: Ah(10240) Bh(10240) = 20480
// =======================================================================
#define A_PITCH 40
#define G_STAGE 20480
#define G_SMEM (3*G_STAGE)

// epi: 0 = bias -> fp16 out; 1 = bias + add -> f32 out; 2 = bias + gelu -> fp16 out
__device__ __forceinline__ void gemm_body(
    const uint16_t* __restrict__ Ah, const uint16_t* __restrict__ Bh,
    const float* __restrict__ bias, const float* __restrict__ add,
    float* __restrict__ Cf, uint16_t* __restrict__ Ch,
    int N, int K, int epi, int bm, int bn, char* sm)
{
    const int tid = threadIdx.x;
    const int wid = tid >> 5;
    const int lane = tid & 31;
    const int wm = wid & 1;
    const int wn = wid >> 1;
    const int fr = lane >> 2;
    const int fkc = (lane & 3) * 2;
    const uint32_t sb = smem_u32(sm);

    float acc[4][4][4];
    #pragma unroll
    for (int tm = 0; tm < 4; tm++)
        #pragma unroll
        for (int tn = 0; tn < 4; tn++)
            #pragma unroll
            for (int i = 0; i < 4; i++) acc[tm][tn][i] = 0.f;

    const int nChunks = K >> 5;

    auto issue = [&](int st, int kt) {
        uint32_t base = sb + st * G_STAGE;
        #pragma unroll
        for (int t = 0; t < 2; t++) {
            int idx = tid + t * 256;
            int row = idx >> 2, c4 = idx & 3;
            size_t ga = (size_t)(bm + row) * K + kt + c4 * 8;
            cp16(base + row * 80 + c4 * 16, Ah + ga);
            size_t gb = (size_t)(bn + row) * K + kt + c4 * 8;
            cp16(base + 10240 + row * 80 + c4 * 16, Bh + gb);
        }
        cp_commit();
    };

    issue(0, 0);
    issue(1, 32);

    for (int chunk = 0; chunk < nChunks; chunk++) {
        if (chunk + 2 < nChunks) {
            issue((chunk + 2) % 3, (chunk + 2) << 5);
            cp_wait2();
        } else if (chunk + 1 < nChunks) {
            cp_wait1();
        } else {
            cp_wait0();
        }
        __syncthreads();

        const char* stg = sm + (chunk % 3) * G_STAGE;
        const uint16_t* sAh = (const uint16_t*)(stg);
        const uint16_t* sBh = (const uint16_t*)(stg + 10240);

        #pragma unroll
        for (int ks = 0; ks < 2; ks++) {
            const int K0 = ks * 16;
            uint32_t ah[4][4];
            #pragma unroll
            for (int tm = 0; tm < 4; tm++) {
                int base = (wm * 64 + tm * 16 + fr) * A_PITCH + K0 + fkc;
                ah[tm][0] = *(const uint32_t*)&sAh[base];
                ah[tm][1] = *(const uint32_t*)&sAh[base + 8 * A_PITCH];
                ah[tm][2] = *(const uint32_t*)&sAh[base + 8];
                ah[tm][3] = *(const uint32_t*)&sAh[base + 8 * A_PITCH + 8];
            }
            uint32_t bh[4][2];
            #pragma unroll
            for (int tn = 0; tn < 4; tn++) {
                int nb = (wn * 32 + tn * 8 + fr) * A_PITCH + K0 + fkc;
                bh[tn][0] = *(const uint32_t*)&sBh[nb];
                bh[tn][1] = *(const uint32_t*)&sBh[nb + 8];
            }
            #pragma unroll
            for (int tm = 0; tm < 4; tm++)
                #pragma unroll
                for (int tn = 0; tn < 4; tn++)
                    mma_f16(acc[tm][tn], ah[tm], bh[tn]);
        }
        __syncthreads();
    }

    #pragma unroll
    for (int tm = 0; tm < 4; tm++) {
        #pragma unroll
        for (int tn = 0; tn < 4; tn++) {
            int row0 = bm + wm * 64 + tm * 16 + fr;
            int col = bn + wn * 32 + tn * 8 + fkc;
            float b0 = bias[col], b1 = bias[col + 1];
            #pragma unroll
            for (int half = 0; half < 2; half++) {
                int row = row0 + half * 8;
                float v0 = acc[tm][tn][half * 2 + 0] + b0;
                float v1 = acc[tm][tn][half * 2 + 1] + b1;
                if (epi == 1) {
                    const float* ap = add + (size_t)row * N + col;
                    v0 += ap[0]; v1 += ap[1];
                    *(float2*)(Cf + (size_t)row * N + col) = make_float2(v0, v1);
                } else {
                    if (epi == 2) {
                        float u = v0;
                        v0 = 0.5f * u * (1.0f + tanhf(GELU_CF * (u + 0.044715f * u * u * u)));
                        u = v1;
                        v1 = 0.5f * u * (1.0f + tanhf(GELU_CF * (u + 0.044715f * u * u * u)));
                    }
                    *(uint32_t*)&Ch[(size_t)row * N + col] = hpack2(v0, v1);
                }
            }
        }
    }
}

__global__ __launch_bounds__(256, 2) void gemm_split(
    const uint16_t* __restrict__ Ah, const uint16_t* __restrict__ Bh,
    const float* __restrict__ bias, const float* __restrict__ add,
    float* __restrict__ Cf, uint16_t* __restrict__ Ch,
    int N, int K, int epi)
{
    extern __shared__ char sm[];
    gemm_body(Ah, Bh, bias, add, Cf, Ch, N, K, epi,
              blockIdx.y * 128, blockIdx.x * 128, sm);
}

__global__ __launch_bounds__(256, 2) void gemm_qkv(
    const float* __restrict__ bq, const float* __restrict__ bk,
    const float* __restrict__ bv, int lw)
{
    extern __shared__ char sm[];
    const int z = blockIdx.z;
    const uint16_t* Bh;
    const float* bias;
    uint16_t* Ch;
    if (z == 0)      { Bh = s_Wq_h + lw; bias = bq; Ch = s_q_h; }
    else if (z == 1) { Bh = s_Wk_h + lw; bias = bk; Ch = s_k_h; }
    else             { Bh = s_Wv_h + lw; bias = bv; Ch = s_v_h; }
    gemm_body(s_x_h, Bh, bias, nullptr, nullptr, Ch,
              D_MODEL, D_MODEL, 0, blockIdx.y * 128, blockIdx.x * 128, sm);
}

// =======================================================================
// Flash attention, 2-way split-KV, pure fp16 operands.
// Stage: Kh(9216) VTh(9216) = 18432; 2 stages.
// =======================================================================
#define KP 72
#define F_STAGE 18432
#define F_SMEM (2*F_STAGE)

__global__ __launch_bounds__(256, 2) void flash_split(
    const float* __restrict__ tau, const float* __restrict__ delta)
{
    extern __shared__ char sm[];
    const uint32_t sb = smem_u32(sm);
    const int tid = threadIdx.x;
    const int wid = tid >> 5;
    const int lane = tid & 31;
    const int fr = lane >> 2;
    const int fkc = (lane & 3) * 2;

    const int nLt = gridDim.x >> 1;
    const int lt = nLt - 1 - (blockIdx.x >> 1);
    const int z = blockIdx.x & 1;
    const int bh = blockIdx.y;
    const int b = bh >> 3, h = bh & 7;
    const int qrow0 = lt * 128;
    const int rA = qrow0 + wid * 16 + fr;
    const int rB = rA + 8;

    uint32_t qh[4][4];
    #pragma unroll
    for (int ks = 0; ks < 4; ks++) {
        int e0 = ks * 16 + fkc;
        size_t oA = (size_t)(b * SEQ + rA) * D_MODEL + h * EDIM + e0;
        size_t oB = (size_t)(b * SEQ + rB) * D_MODEL + h * EDIM + e0;
        qh[ks][0] = *(const uint32_t*)&s_q_h[oA];
        qh[ks][1] = *(const uint32_t*)&s_q_h[oB];
        qh[ks][2] = *(const uint32_t*)&s_q_h[oA + 8];
        qh[ks][3] = *(const uint32_t*)&s_q_h[oB + 8];
    }

    float oacc[8][4];
    #pragma unroll
    for (int t = 0; t < 8; t++)
        #pragma unroll
        for (int i = 0; i < 4; i++) oacc[t][i] = 0.f;
    float m0 = -3.0e38f, m1 = -3.0e38f;
    float l0 = 0.f, l1 = 0.f;
    const float sct = 0.125f * __ldg(&tau[b]);

    const int stStart = z * (lt + 1);
    const int nTiles = lt + 1;

    auto issue = [&](int stage, int key_base) {
        uint32_t base = sb + stage * F_STAGE;
        {
            int row = tid >> 2, c4 = tid & 3;
            size_t gk = (size_t)(b * SEQ + key_base + row) * D_MODEL + h * EDIM + c4 * 16;
            uint32_t dk = base + row * 144 + c4 * 32;
            cp16(dk, s_k_h + gk);
            cp16(dk + 16, s_k_h + gk + 8);
            size_t gv = ((size_t)bh * EDIM + row) * SEQ + key_base + c4 * 16;
            uint32_t dv = base + 9216 + row * 144 + c4 * 32;
            cp16(dv, s_vT_h + gv);
            cp16(dv + 16, s_vT_h + gv + 8);
        }
        cp_commit();
    };

    issue(0, stStart * 64);

    for (int it = 0; it < nTiles; it++) {
        const int key_base = (stStart + it) * 64;
        if (it + 1 < nTiles) {
            issue((it + 1) & 1, key_base + 64);
            cp_wait1();
        } else {
            cp_wait0();
        }
        __syncthreads();

        const char* stg = sm + (it & 1) * F_STAGE;
        const uint16_t* sKh  = (const uint16_t*)(stg);
        const uint16_t* sVTh = (const uint16_t*)(stg + 9216);

        // ---- S = Q K^T ----
        float s[8][4];
        #pragma unroll
        for (int t = 0; t < 8; t++)
            #pragma unroll
            for (int i = 0; i < 4; i++) s[t][i] = 0.f;

        #pragma unroll
        for (int ks = 0; ks < 4; ks++) {
            const int K0 = ks * 16;
            #pragma unroll
            for (int tn = 0; tn < 8; tn++) {
                int base = (tn * 8 + fr) * KP + K0 + fkc;
                uint32_t bhh[2];
                bhh[0] = *(const uint32_t*)&sKh[base];
                bhh[1] = *(const uint32_t*)&sKh[base + 8];
                mma_f16(s[tn], qh[ks], bhh);
            }
        }

        // ---- scale + bias + mask ----
        const bool masked = (key_base + 63) > qrow0;
        #pragma unroll
        for (int tn = 0; tn < 8; tn++) {
            int key = key_base + tn * 8 + fkc;
            float2 dd = *(const float2*)(delta + b * SEQ + key);
            float d0 = 0.125f * dd.x, d1 = 0.125f * dd.y;
            s[tn][0] = fmaf(s[tn][0], sct, d0);
            s[tn][1] = fmaf(s[tn][1], sct, d1);
            s[tn][2] = fmaf(s[tn][2], sct, d0);
            s[tn][3] = fmaf(s[tn][3], sct, d1);
            if (masked) {
                if (key     > rA) s[tn][0] = -1e30f;
                if (key + 1 > rA) s[tn][1] = -1e30f;
                if (key     > rB) s[tn][2] = -1e30f;
                if (key + 1 > rB) s[tn][3] = -1e30f;
            }
        }

        // ---- online softmax ----
        float r0 = -3.0e38f, r1 = -3.0e38f;
        #pragma unroll
        for (int tn = 0; tn < 8; tn++) {
            r0 = fmaxf(r0, fmaxf(s[tn][0], s[tn][1]));
            r1 = fmaxf(r1, fmaxf(s[tn][2], s[tn][3]));
        }
        r0 = fmaxf(r0, __shfl_xor_sync(~0u, r0, 1));
        r0 = fmaxf(r0, __shfl_xor_sync(~0u, r0, 2));
        r1 = fmaxf(r1, __shfl_xor_sync(~0u, r1, 1));
        r1 = fmaxf(r1, __shfl_xor_sync(~0u, r1, 2));
        float mn0 = fmaxf(m0, r0), mn1 = fmaxf(m1, r1);
        float sc0 = __expf(m0 - mn0), sc1 = __expf(m1 - mn1);
        float sum0 = 0.f, sum1 = 0.f;
        #pragma unroll
        for (int tn = 0; tn < 8; tn++) {
            s[tn][0] = __expf(s[tn][0] - mn0); sum0 += s[tn][0];
            s[tn][1] = __expf(s[tn][1] - mn0); sum0 += s[tn][1];
            s[tn][2] = __expf(s[tn][2] - mn1); sum1 += s[tn][2];
            s[tn][3] = __expf(s[tn][3] - mn1); sum1 += s[tn][3];
        }
        sum0 += __shfl_xor_sync(~0u, sum0, 1);
        sum0 += __shfl_xor_sync(~0u, sum0, 2);
        sum1 += __shfl_xor_sync(~0u, sum1, 1);
        sum1 += __shfl_xor_sync(~0u, sum1, 2);
        l0 = l0 * sc0 + sum0; m0 = mn0;
        l1 = l1 * sc1 + sum1; m1 = mn1;
        #pragma unroll
        for (int t = 0; t < 8; t++) {
            oacc[t][0] *= sc0; oacc[t][1] *= sc0;
            oacc[t][2] *= sc1; oacc[t][3] *= sc1;
        }

        // ---- O += P V ----
        #pragma unroll
        for (int kc = 0; kc < 4; kc++) {
            uint32_t ah[4];
            ah[0] = hpack2(s[2*kc][0],   s[2*kc][1]);
            ah[1] = hpack2(s[2*kc][2],   s[2*kc][3]);
            ah[2] = hpack2(s[2*kc+1][0], s[2*kc+1][1]);
            ah[3] = hpack2(s[2*kc+1][2], s[2*kc+1][3]);
            #pragma unroll
            for (int tn2 = 0; tn2 < 8; tn2++) {
                int vb = (tn2 * 8 + fr) * KP + kc * 16 + fkc;
                uint32_t bvh[2];
                bvh[0] = *(const uint32_t*)&sVTh[vb];
                bvh[1] = *(const uint32_t*)&sVTh[vb + 8];
                mma_f16(oacc[tn2], ah, bvh);
            }
        }
        __syncthreads();
    }

    // ---- write partials ----
    float* po = z ? g_po1 : g_po0;
    float* ml = z ? g_ml1 : g_ml0;
    #pragma unroll
    for (int tn2 = 0; tn2 < 8; tn2++) {
        int col = h * EDIM + tn2 * 8 + fkc;
        *(float2*)&po[(size_t)(b * SEQ + rA) * D_MODEL + col] = make_float2(oacc[tn2][0], oacc[tn2][1]);
        *(float2*)&po[(size_t)(b * SEQ + rB) * D_MODEL + col] = make_float2(oacc[tn2][2], oacc[tn2][3]);
    }
    if ((lane & 3) == 0) {
        *(float2*)&ml[(size_t)(bh * SEQ + rA) * 2] = make_float2(m0, l0);
        *(float2*)&ml[(size_t)(bh * SEQ + rB) * 2] = make_float2(m1, l1);
    }
}

// merge split-KV partials -> fp16 attn output
__global__ __launch_bounds__(256) void merge_k()
{
    const int idx2 = (blockIdx.x * 256 + threadIdx.x) * 2;
    const int r = idx2 >> 9;
    const int d = idx2 & 511;
    const int bh = ((r >> 11) << 3) | (d >> 6);
    const int srow = r & (SEQ - 1);
    float2 ml0 = *(float2*)&g_ml0[(size_t)(bh * SEQ + srow) * 2];
    float2 ml1 = *(float2*)&g_ml1[(size_t)(bh * SEQ + srow) * 2];
    float M = fmaxf(ml0.x, ml1.x);
    float w0 = __expf(ml0.x - M), w1 = __expf(ml1.x - M);
    float inv = 1.0f / (ml0.y * w0 + ml1.y * w1);
    float2 p0 = *(float2*)&g_po0[idx2];
    float2 p1 = *(float2*)&g_po1[idx2];
    float v0 = (p0.x * w0 + p1.x * w1) * inv;
    float v1 = (p0.y * w0 + p1.y * w1) * inv;
    *(uint32_t*)&s_attn_h[idx2] = hpack2(v0, v1);
}

// ---------------- LayerNorm (+ optional fp16 output) ----------------
__global__ __launch_bounds__(128) void ln_k(
    const float* __restrict__ x, const float* __restrict__ g,
    const float* __restrict__ bb, float* __restrict__ y,
    uint16_t* __restrict__ yh)
{
    const int row = blockIdx.x;
    const float* p = x + (size_t)row * D_MODEL;
    const int tid = threadIdx.x;
    float4 v = *(const float4*)(p + tid * 4);
    float s = v.x + v.y + v.z + v.w;
    __shared__ float sh[4];
    #pragma unroll
    for (int o = 16; o > 0; o >>= 1) s += __shfl_xor_sync(~0u, s, o);
    if ((tid & 31) == 0) sh[tid >> 5] = s;
    __syncthreads();
    s = sh[0] + sh[1] + sh[2] + sh[3];
    const float mean = s * (1.0f / (float)D_MODEL);
    float vs = (v.x - mean) * (v.x - mean) + (v.y - mean) * (v.y - mean)
             + (v.z - mean) * (v.z - mean) + (v.w - mean) * (v.w - mean);
    #pragma unroll
    for (int o = 16; o > 0; o >>= 1) vs += __shfl_xor_sync(~0u, vs, o);
    __syncthreads();
    if ((tid & 31) == 0) sh[tid >> 5] = vs;
    __syncthreads();
    vs = sh[0] + sh[1] + sh[2] + sh[3];
    const float rstd = rsqrtf(vs * (1.0f / (float)D_MODEL) + 1e-5f);
    const int col = tid * 4;
    const float4 gg = *(const float4*)(g + col);
    const float4 bbv = *(const float4*)(bb + col);
    float4 out;
    out.x = (v.x - mean) * rstd * gg.x + bbv.x;
    out.y = (v.y - mean) * rstd * gg.y + bbv.y;
    out.z = (v.z - mean) * rstd * gg.z + bbv.z;
    out.w = (v.w - mean) * rstd * gg.w + bbv.w;
    *(float4*)(y + (size_t)row * D_MODEL + col) = out;
    if (yh != nullptr) {
        size_t o = (size_t)row * D_MODEL + col;
        *(uint32_t*)&yh[o]     = hpack2(out.x, out.y);
        *(uint32_t*)&yh[o + 2] = hpack2(out.z, out.w);
    }
}

// ---------------- orchestration ----------------
extern "C" void kernel_launch(void* const* d_in, const int* in_sizes, int n_in,
                              void* d_out, int out_size)
{
    const float* x_in  = (const float*)d_in[0];
    const float* tau   = (const float*)d_in[1];
    const float* delta = (const float*)d_in[2];
    const float* Wq = (const float*)d_in[4];
    const float* bq = (const float*)d_in[5];
    const float* Wk = (const float*)d_in[6];
    const float* bk = (const float*)d_in[7];
    const float* Wv = (const float*)d_in[8];
    const float* bv = (const float*)d_in[9];
    const float* Wo = (const float*)d_in[10];
    const float* bo = (const float*)d_in[11];
    const float* W1 = (const float*)d_in[12];
    const float* b1 = (const float*)d_in[13];
    const float* W2 = (const float*)d_in[14];
    const float* b2 = (const float*)d_in[15];
    const float* ln1g = (const float*)d_in[16];
    const float* ln1b = (const float*)d_in[17];
    const float* ln2g = (const float*)d_in[18];
    const float* ln2b = (const float*)d_in[19];
    const float* lnfg = (const float*)d_in[20];
    const float* lnfb = (const float*)d_in[21];

    float *gx, *gxb, *go;
    cudaGetSymbolAddress((void**)&gx,  g_x);
    cudaGetSymbolAddress((void**)&gxb, g_xb);
    cudaGetSymbolAddress((void**)&go,  g_o);

    uint16_t *axh, *axbh, *ahh, *aath;
    cudaGetSymbolAddress((void**)&axh,  s_x_h);
    cudaGetSymbolAddress((void**)&axbh, s_xb_h);
    cudaGetSymbolAddress((void**)&ahh,  s_h_h);
    cudaGetSymbolAddress((void**)&aath, s_attn_h);

    uint16_t *wo_h, *w1_h, *w2_h;
    cudaGetSymbolAddress((void**)&wo_h, s_Wo_h);
    cudaGetSymbolAddress((void**)&w1_h, s_W1_h);
    cudaGetSymbolAddress((void**)&w2_h, s_W2_h);

    cudaFuncSetAttribute(gemm_split,  cudaFuncAttributeMaxDynamicSharedMemorySize, G_SMEM);
    cudaFuncSetAttribute(gemm_qkv,    cudaFuncAttributeMaxDynamicSharedMemorySize, G_SMEM);
    cudaFuncSetAttribute(flash_split, cudaFuncAttributeMaxDynamicSharedMemorySize, F_SMEM);

    transp_split<<<dim3(64, 64, 12), 256>>>(Wq, Wk, Wv, Wo, W1, W2);
    split_x<<<ROWS * D_MODEL / 1024, 256>>>(x_in);

    const dim3 gProj(D_MODEL / 128, ROWS / 128);       // (4, 32)
    const dim3 gQKV(D_MODEL / 128, ROWS / 128, 3);     // (4, 32, 3)
    const dim3 gFF1(D_FF / 128, ROWS / 128);           // (16, 32)
    const dim3 gFlash(2 * SEQ / 128, BH);              // (32, 16)
    const dim3 gVT(SEQ / 32, BH);                      // (64, 16)

    for (int l = 0; l < 2; l++) {
        const int wOff   = l * D_MODEL * D_MODEL;
        const int w1Off  = l * D_MODEL * D_FF;
        const size_t bOff  = (size_t)l * D_MODEL;
        const size_t b1Off = (size_t)l * D_FF;

        gemm_qkv<<<gQKV, 256, G_SMEM>>>(bq + bOff, bk + bOff, bv + bOff, wOff);
        vtransp<<<gVT, 256>>>();
        flash_split<<<gFlash, 256, F_SMEM>>>(tau, delta);
        merge_k<<<ROWS * D_MODEL / 512, 256>>>();

        gemm_split<<<gProj, 256, G_SMEM>>>(aath, wo_h + wOff,
                                           bo + bOff, gx, gx, nullptr,
                                           D_MODEL, D_MODEL, 1);
        ln_k<<<ROWS, 128>>>(gx, ln1g + bOff, ln1b + bOff, gxb, axbh);

        gemm_split<<<gFF1, 256, G_SMEM>>>(axbh, w1_h + w1Off,
                                          b1 + b1Off, nullptr, nullptr, ahh,
                                          D_FF, D_MODEL, 2);
        gemm_split<<<gProj, 256, G_SMEM>>>(ahh, w2_h + w1Off,
                                           b2 + bOff, gxb, go, nullptr,
                                           D_MODEL, D_FF, 1);
        ln_k<<<ROWS, 128>>>(go, ln2g + bOff, ln2b + bOff, gx, axh);
    }
    ln_k<<<ROWS, 128>>>(gx, lnfg, lnfb, (float*)d_out, nullptr);
}

// round 9
// speedup vs baseline: 2.3372x; 1.0317x over previous
#include <cuda_runtime.h>
#include <cuda_fp16.h>
#include <math.h>
#include <stdint.h>

#define D_MODEL 512
#define D_FF 2048
#define BATCH 2
#define SEQ 2048
#define NHEADS 8
#define EDIM 64
#define ROWS (BATCH*SEQ)
#define BH (BATCH*NHEADS)
#define GELU_CF 0.7978845608028654f
#define WSZ  (2*D_MODEL*D_MODEL)
#define W1SZ (2*D_MODEL*D_FF)

// ---------------- f32 scratch ----------------
__device__ float g_x[ROWS*D_MODEL];
__device__ float g_xb[ROWS*D_MODEL];
__device__ float g_o[ROWS*D_MODEL];
__device__ float g_po0[ROWS*D_MODEL];
__device__ float g_po1[ROWS*D_MODEL];
__device__ float g_ml0[BH*SEQ*2];
__device__ float g_ml1[BH*SEQ*2];

// ---------------- fp16 TRANSPOSED weights ([layer][N][K]) ----------------
__device__ uint16_t s_Wq_h[WSZ];
__device__ uint16_t s_Wk_h[WSZ];
__device__ uint16_t s_Wv_h[WSZ];
__device__ uint16_t s_Wo_h[WSZ];
__device__ uint16_t s_W1_h[W1SZ];
__device__ uint16_t s_W2_h[W1SZ];

// ---------------- fp16 activations ----------------
__device__ uint16_t s_x_h[ROWS*D_MODEL];
__device__ uint16_t s_xb_h[ROWS*D_MODEL];
__device__ uint16_t s_q_h[ROWS*D_MODEL];
__device__ uint16_t s_k_h[ROWS*D_MODEL];
__device__ uint16_t s_v_h[ROWS*D_MODEL];
__device__ uint16_t s_vT_h[ROWS*D_MODEL];   // [bh][e][tok]
__device__ uint16_t s_attn_h[ROWS*D_MODEL];
__device__ uint16_t s_h_h[ROWS*D_FF];

// =======================================================================
// helpers
// =======================================================================
__device__ __forceinline__ uint32_t hpack2(float x0, float x1) {
    __half2 hh = __floats2half2_rn(x0, x1);
    return *reinterpret_cast<uint32_t*>(&hh);
}

__device__ __forceinline__ void mma_f16(float* c, const uint32_t* a, const uint32_t* b) {
    asm volatile(
        "mma.sync.aligned.m16n8k16.row.col.f32.f16.f16.f32 "
        "{%0,%1,%2,%3}, {%4,%5,%6,%7}, {%8,%9}, {%0,%1,%2,%3};"
        : "+f"(c[0]), "+f"(c[1]), "+f"(c[2]), "+f"(c[3])
        : "r"(a[0]), "r"(a[1]), "r"(a[2]), "r"(a[3]), "r"(b[0]), "r"(b[1]));
}

__device__ __forceinline__ void ldsm_x4(uint32_t* r, uint32_t addr) {
    asm volatile("ldmatrix.sync.aligned.m8n8.x4.shared.b16 {%0,%1,%2,%3}, [%4];"
        : "=r"(r[0]), "=r"(r[1]), "=r"(r[2]), "=r"(r[3]) : "r"(addr));
}

__device__ __forceinline__ uint32_t smem_u32(const void* p) {
    uint32_t a;
    asm("{ .reg .u64 t; cvta.to.shared.u64 t, %1; cvt.u32.u64 %0, t; }"
        : "=r"(a) : "l"(p));
    return a;
}

__device__ __forceinline__ void cp16(uint32_t dst, const void* src) {
    asm volatile("cp.async.cg.shared.global [%0], [%1], 16;\n" :: "r"(dst), "l"(src));
}
__device__ __forceinline__ void cp_commit() {
    asm volatile("cp.async.commit_group;\n" ::: "memory");
}
__device__ __forceinline__ void cp_wait2() {
    asm volatile("cp.async.wait_group 2;\n" ::: "memory");
}
__device__ __forceinline__ void cp_wait1() {
    asm volatile("cp.async.wait_group 1;\n" ::: "memory");
}
__device__ __forceinline__ void cp_wait0() {
    asm volatile("cp.async.wait_group 0;\n" ::: "memory");
}

// =======================================================================
// prologue
// =======================================================================
__global__ __launch_bounds__(256) void transp_split(
    const float* __restrict__ Wq, const float* __restrict__ Wk,
    const float* __restrict__ Wv, const float* __restrict__ Wo,
    const float* __restrict__ W1, const float* __restrict__ W2)
{
    const int w = blockIdx.z >> 1, layer = blockIdx.z & 1;
    const float* src; uint16_t* dh; int K, N;
    switch (w) {
        case 0: src = Wq; dh = s_Wq_h; K = 512;  N = 512;  break;
        case 1: src = Wk; dh = s_Wk_h; K = 512;  N = 512;  break;
        case 2: src = Wv; dh = s_Wv_h; K = 512;  N = 512;  break;
        case 3: src = Wo; dh = s_Wo_h; K = 512;  N = 512;  break;
        case 4: src = W1; dh = s_W1_h; K = 512;  N = 2048; break;
        default: src = W2; dh = s_W2_h; K = 2048; N = 512; break;
    }
    const int k0 = blockIdx.x * 32, n0 = blockIdx.y * 32;
    if (k0 >= K || n0 >= N) return;
    src += (size_t)layer * K * N;
    dh  += (size_t)layer * K * N;

    __shared__ float t[32][33];
    const int tid = threadIdx.x;
    const int tx = tid & 31, ty = tid >> 5;
    #pragma unroll
    for (int i = 0; i < 4; i++) {
        int k = ty + i * 8;
        t[k][tx] = src[(size_t)(k0 + k) * N + n0 + tx];
    }
    __syncthreads();
    const int n = tid >> 3, kq = tid & 7;
    float a0 = t[kq*4+0][n], a1 = t[kq*4+1][n], a2 = t[kq*4+2][n], a3 = t[kq*4+3][n];
    size_t o = (size_t)(n0 + n) * K + k0 + kq * 4;
    *(uint32_t*)&dh[o]     = hpack2(a0, a1);
    *(uint32_t*)&dh[o + 2] = hpack2(a2, a3);
}

__global__ __launch_bounds__(256) void split_x(const float* __restrict__ x)
{
    int idx = (blockIdx.x * 256 + threadIdx.x) * 4;
    float4 v = *(const float4*)(x + idx);
    *(float4*)(g_x + idx) = v;
    *(uint32_t*)&s_x_h[idx]     = hpack2(v.x, v.y);
    *(uint32_t*)&s_x_h[idx + 2] = hpack2(v.z, v.w);
}

// V transpose: s_v_h [tok][h*64+e] -> s_vT_h [bh][e][tok]
__global__ __launch_bounds__(256) void vtransp()
{
    __shared__ uint16_t tt[32][66];
    const int bh = blockIdx.y;
    const int b = bh >> 3, h = bh & 7;
    const int tok0 = blockIdx.x * 32;
    const int tid = threadIdx.x;
    #pragma unroll
    for (int i = 0; i < 4; i++) {
        int idx = tid + i * 256;
        int r = idx >> 5, c = idx & 31;
        uint32_t v = *(const uint32_t*)&s_v_h[(size_t)(b * SEQ + tok0 + r) * D_MODEL + h * 64 + c * 2];
        *(uint32_t*)&tt[r][c * 2] = v;
    }
    __syncthreads();
    #pragma unroll
    for (int i = 0; i < 4; i++) {
        int idx = tid + i * 256;
        int e = idx >> 4, t2 = idx & 15;
        uint32_t v = (uint32_t)tt[t2 * 2][e] | ((uint32_t)tt[t2 * 2 + 1][e] << 16);
        *(uint32_t*)&s_vT_h[((size_t)bh * EDIM + e) * SEQ + tok0 + t2 * 2] = v;
    }
}

// =======================================================================
// GEMM: pure fp16, ldmatrix frags. A [M][K], B (transposed weights) [N][K].
// Block tile 128 x (TN*32). 256 thr. 3-stage cp.async pipeline.
// Stage: A(10240) + B(TN*2560)
// =======================================================================
#define A_PITCH 40

// epi: 0 = bias -> fp16 out; 1 = bias + add -> f32 out; 2 = bias + gelu -> fp16 out
template<int TN>
__device__ __forceinline__ void gemm_body(
    const uint16_t* __restrict__ Ah, const uint16_t* __restrict__ Bh,
    const float* __restrict__ bias, const float* __restrict__ add,
    float* __restrict__ Cf, uint16_t* __restrict__ Ch,
    int N, int K, int epi, int bm, int bn, char* sm)
{
    constexpr int STAGE = 10240 + TN * 2560;
    constexpr int NP = TN / 2;
    const int tid = threadIdx.x;
    const int wid = tid >> 5;
    const int lane = tid & 31;
    const int wm = wid & 1;
    const int wn = wid >> 1;
    const int fr = lane >> 2;
    const int fkc = (lane & 3) * 2;
    const int mi = lane >> 3, ri = lane & 7;
    const uint32_t sb = smem_u32(sm);

    // per-lane ldmatrix byte offsets (within stage)
    int aoff[4];
    #pragma unroll
    for (int tm = 0; tm < 4; tm++)
        aoff[tm] = ((wm * 64 + tm * 16 + (mi & 1) * 8 + ri) * A_PITCH + (mi >> 1) * 8) * 2;
    int boff[NP];
    #pragma unroll
    for (int p = 0; p < NP; p++)
        boff[p] = ((wn * (TN * 8) + (p * 2 + (mi >> 1)) * 8 + ri) * A_PITCH + (mi & 1) * 8) * 2;

    float acc[4][TN][4];
    #pragma unroll
    for (int tm = 0; tm < 4; tm++)
        #pragma unroll
        for (int tn = 0; tn < TN; tn++)
            #pragma unroll
            for (int i = 0; i < 4; i++) acc[tm][tn][i] = 0.f;

    const int nChunks = K >> 5;

    auto issue = [&](int st, int kt) {
        uint32_t base = sb + st * STAGE;
        #pragma unroll
        for (int t = 0; t < 2 + NP; t++) {
            int idx = tid + t * 256;
            if (idx < 512) {
                int row = idx >> 2, c4 = idx & 3;
                cp16(base + row * 80 + c4 * 16, Ah + (size_t)(bm + row) * K + kt + c4 * 8);
            } else {
                int j = idx - 512;
                int row = j >> 2, c4 = j & 3;
                cp16(base + 10240 + row * 80 + c4 * 16, Bh + (size_t)(bn + row) * K + kt + c4 * 8);
            }
        }
        cp_commit();
    };

    issue(0, 0);
    issue(1, 32);

    for (int chunk = 0; chunk < nChunks; chunk++) {
        if (chunk + 2 < nChunks) {
            issue((chunk + 2) % 3, (chunk + 2) << 5);
            cp_wait2();
        } else if (chunk + 1 < nChunks) {
            cp_wait1();
        } else {
            cp_wait0();
        }
        __syncthreads();

        const uint32_t stgA = sb + (chunk % 3) * STAGE;
        const uint32_t stgB = stgA + 10240;

        #pragma unroll
        for (int ks = 0; ks < 2; ks++) {
            const int K0b = ks * 32;   // bytes: 16 u16
            uint32_t ah[4][4];
            #pragma unroll
            for (int tm = 0; tm < 4; tm++)
                ldsm_x4(ah[tm], stgA + aoff[tm] + K0b);
            uint32_t bhf[TN][2];
            #pragma unroll
            for (int p = 0; p < NP; p++) {
                uint32_t r[4];
                ldsm_x4(r, stgB + boff[p] + K0b);
                bhf[p*2][0] = r[0]; bhf[p*2][1] = r[1];
                bhf[p*2+1][0] = r[2]; bhf[p*2+1][1] = r[3];
            }
            #pragma unroll
            for (int tm = 0; tm < 4; tm++)
                #pragma unroll
                for (int tn = 0; tn < TN; tn++)
                    mma_f16(acc[tm][tn], ah[tm], bhf[tn]);
        }
        __syncthreads();
    }

    #pragma unroll
    for (int tm = 0; tm < 4; tm++) {
        #pragma unroll
        for (int tn = 0; tn < TN; tn++) {
            int row0 = bm + wm * 64 + tm * 16 + fr;
            int col = bn + wn * (TN * 8) + tn * 8 + fkc;
            float b0 = bias[col], b1 = bias[col + 1];
            #pragma unroll
            for (int half = 0; half < 2; half++) {
                int row = row0 + half * 8;
                float v0 = acc[tm][tn][half * 2 + 0] + b0;
                float v1 = acc[tm][tn][half * 2 + 1] + b1;
                if (epi == 1) {
                    const float* ap = add + (size_t)row * N + col;
                    v0 += ap[0]; v1 += ap[1];
                    *(float2*)(Cf + (size_t)row * N + col) = make_float2(v0, v1);
                } else {
                    if (epi == 2) {
                        float u = v0;
                        v0 = 0.5f * u * (1.0f + tanhf(GELU_CF * (u + 0.044715f * u * u * u)));
                        u = v1;
                        v1 = 0.5f * u * (1.0f + tanhf(GELU_CF * (u + 0.044715f * u * u * u)));
                    }
                    *(uint32_t*)&Ch[(size_t)row * N + col] = hpack2(v0, v1);
                }
            }
        }
    }
}

template<int TN>
__global__ __launch_bounds__(256, 2) void gemm_split_t(
    const uint16_t* __restrict__ Ah, const uint16_t* __restrict__ Bh,
    const float* __restrict__ bias, const float* __restrict__ add,
    float* __restrict__ Cf, uint16_t* __restrict__ Ch,
    int N, int K, int epi)
{
    extern __shared__ char sm[];
    gemm_body<TN>(Ah, Bh, bias, add, Cf, Ch, N, K, epi,
                  blockIdx.y * 128, blockIdx.x * (TN * 32), sm);
}

__global__ __launch_bounds__(256, 2) void gemm_qkv(
    const float* __restrict__ bq, const float* __restrict__ bk,
    const float* __restrict__ bv, int lw)
{
    extern __shared__ char sm[];
    const int z = blockIdx.z;
    const uint16_t* Bh;
    const float* bias;
    uint16_t* Ch;
    if (z == 0)      { Bh = s_Wq_h + lw; bias = bq; Ch = s_q_h; }
    else if (z == 1) { Bh = s_Wk_h + lw; bias = bk; Ch = s_k_h; }
    else             { Bh = s_Wv_h + lw; bias = bv; Ch = s_v_h; }
    gemm_body<4>(s_x_h, Bh, bias, nullptr, nullptr, Ch,
                 D_MODEL, D_MODEL, 0, blockIdx.y * 128, blockIdx.x * 128, sm);
}

// =======================================================================
// Flash attention, 2-way split-KV, pure fp16, ldmatrix frags.
// Stage: Kh(9216) VTh(9216) = 18432; 2 stages.
// =======================================================================
#define KP 72
#define F_STAGE 18432
#define F_SMEM (2*F_STAGE)

__global__ __launch_bounds__(256, 2) void flash_split(
    const float* __restrict__ tau, const float* __restrict__ delta)
{
    extern __shared__ char sm[];
    const uint32_t sb = smem_u32(sm);
    const int tid = threadIdx.x;
    const int wid = tid >> 5;
    const int lane = tid & 31;
    const int fr = lane >> 2;
    const int fkc = (lane & 3) * 2;
    const int mi = lane >> 3, ri = lane & 7;

    const int nLt = gridDim.x >> 1;
    const int lt = nLt - 1 - (blockIdx.x >> 1);
    const int z = blockIdx.x & 1;
    const int bh = blockIdx.y;
    const int b = bh >> 3, h = bh & 7;
    const int qrow0 = lt * 128;
    const int rA = qrow0 + wid * 16 + fr;
    const int rB = rA + 8;

    // per-lane ldmatrix offsets for K and VT tiles (same layout, pitch KP)
    int koff[4];
    #pragma unroll
    for (int p = 0; p < 4; p++)
        koff[p] = (((p * 2 + (mi >> 1)) * 8 + ri) * KP + (mi & 1) * 8) * 2;

    uint32_t qh[4][4];
    #pragma unroll
    for (int ks = 0; ks < 4; ks++) {
        int e0 = ks * 16 + fkc;
        size_t oA = (size_t)(b * SEQ + rA) * D_MODEL + h * EDIM + e0;
        size_t oB = (size_t)(b * SEQ + rB) * D_MODEL + h * EDIM + e0;
        qh[ks][0] = *(const uint32_t*)&s_q_h[oA];
        qh[ks][1] = *(const uint32_t*)&s_q_h[oB];
        qh[ks][2] = *(const uint32_t*)&s_q_h[oA + 8];
        qh[ks][3] = *(const uint32_t*)&s_q_h[oB + 8];
    }

    float oacc[8][4];
    #pragma unroll
    for (int t = 0; t < 8; t++)
        #pragma unroll
        for (int i = 0; i < 4; i++) oacc[t][i] = 0.f;
    float m0 = -3.0e38f, m1 = -3.0e38f;
    float l0 = 0.f, l1 = 0.f;
    const float sct = 0.125f * __ldg(&tau[b]);

    const int stStart = z * (lt + 1);
    const int nTiles = lt + 1;

    auto issue = [&](int stage, int key_base) {
        uint32_t base = sb + stage * F_STAGE;
        {
            int row = tid >> 2, c4 = tid & 3;
            size_t gk = (size_t)(b * SEQ + key_base + row) * D_MODEL + h * EDIM + c4 * 16;
            uint32_t dk = base + row * 144 + c4 * 32;
            cp16(dk, s_k_h + gk);
            cp16(dk + 16, s_k_h + gk + 8);
            size_t gv = ((size_t)bh * EDIM + row) * SEQ + key_base + c4 * 16;
            uint32_t dv = base + 9216 + row * 144 + c4 * 32;
            cp16(dv, s_vT_h + gv);
            cp16(dv + 16, s_vT_h + gv + 8);
        }
        cp_commit();
    };

    issue(0, stStart * 64);

    for (int it = 0; it < nTiles; it++) {
        const int key_base = (stStart + it) * 64;
        if (it + 1 < nTiles) {
            issue((it + 1) & 1, key_base + 64);
            cp_wait1();
        } else {
            cp_wait0();
        }
        __syncthreads();

        const uint32_t stgK = sb + (it & 1) * F_STAGE;
        const uint32_t stgV = stgK + 9216;

        // ---- S = Q K^T ----
        float s[8][4];
        #pragma unroll
        for (int t = 0; t < 8; t++)
            #pragma unroll
            for (int i = 0; i < 4; i++) s[t][i] = 0.f;

        #pragma unroll
        for (int ks = 0; ks < 4; ks++) {
            uint32_t bf[8][2];
            #pragma unroll
            for (int p = 0; p < 4; p++) {
                uint32_t r[4];
                ldsm_x4(r, stgK + koff[p] + ks * 32);
                bf[p*2][0] = r[0]; bf[p*2][1] = r[1];
                bf[p*2+1][0] = r[2]; bf[p*2+1][1] = r[3];
            }
            #pragma unroll
            for (int tn = 0; tn < 8; tn++)
                mma_f16(s[tn], qh[ks], bf[tn]);
        }

        // ---- scale + bias + mask ----
        const bool masked = (key_base + 63) > qrow0;
        #pragma unroll
        for (int tn = 0; tn < 8; tn++) {
            int key = key_base + tn * 8 + fkc;
            float2 dd = *(const float2*)(delta + b * SEQ + key);
            float d0 = 0.125f * dd.x, d1 = 0.125f * dd.y;
            s[tn][0] = fmaf(s[tn][0], sct, d0);
            s[tn][1] = fmaf(s[tn][1], sct, d1);
            s[tn][2] = fmaf(s[tn][2], sct, d0);
            s[tn][3] = fmaf(s[tn][3], sct, d1);
            if (masked) {
                if (key     > rA) s[tn][0] = -1e30f;
                if (key + 1 > rA) s[tn][1] = -1e30f;
                if (key     > rB) s[tn][2] = -1e30f;
                if (key + 1 > rB) s[tn][3] = -1e30f;
            }
        }

        // ---- online softmax ----
        float r0 = -3.0e38f, r1 = -3.0e38f;
        #pragma unroll
        for (int tn = 0; tn < 8; tn++) {
            r0 = fmaxf(r0, fmaxf(s[tn][0], s[tn][1]));
            r1 = fmaxf(r1, fmaxf(s[tn][2], s[tn][3]));
        }
        r0 = fmaxf(r0, __shfl_xor_sync(~0u, r0, 1));
        r0 = fmaxf(r0, __shfl_xor_sync(~0u, r0, 2));
        r1 = fmaxf(r1, __shfl_xor_sync(~0u, r1, 1));
        r1 = fmaxf(r1, __shfl_xor_sync(~0u, r1, 2));
        float mn0 = fmaxf(m0, r0), mn1 = fmaxf(m1, r1);
        float sc0 = __expf(m0 - mn0), sc1 = __expf(m1 - mn1);
        float sum0 = 0.f, sum1 = 0.f;
        #pragma unroll
        for (int tn = 0; tn < 8; tn++) {
            s[tn][0] = __expf(s[tn][0] - mn0); sum0 += s[tn][0];
            s[tn][1] = __expf(s[tn][1] - mn0); sum0 += s[tn][1];
            s[tn][2] = __expf(s[tn][2] - mn1); sum1 += s[tn][2];
            s[tn][3] = __expf(s[tn][3] - mn1); sum1 += s[tn][3];
        }
        sum0 += __shfl_xor_sync(~0u, sum0, 1);
        sum0 += __shfl_xor_sync(~0u, sum0, 2);
        sum1 += __shfl_xor_sync(~0u, sum1, 1);
        sum1 += __shfl_xor_sync(~0u, sum1, 2);
        l0 = l0 * sc0 + sum0; m0 = mn0;
        l1 = l1 * sc1 + sum1; m1 = mn1;
        #pragma unroll
        for (int t = 0; t < 8; t++) {
            oacc[t][0] *= sc0; oacc[t][1] *= sc0;
            oacc[t][2] *= sc1; oacc[t][3] *= sc1;
        }

        // ---- O += P V ----
        #pragma unroll
        for (int kc = 0; kc < 4; kc++) {
            uint32_t ah[4];
            ah[0] = hpack2(s[2*kc][0],   s[2*kc][1]);
            ah[1] = hpack2(s[2*kc][2],   s[2*kc][3]);
            ah[2] = hpack2(s[2*kc+1][0], s[2*kc+1][1]);
            ah[3] = hpack2(s[2*kc+1][2], s[2*kc+1][3]);
            uint32_t vf[8][2];
            #pragma unroll
            for (int p = 0; p < 4; p++) {
                uint32_t r[4];
                ldsm_x4(r, stgV + koff[p] + kc * 32);
                vf[p*2][0] = r[0]; vf[p*2][1] = r[1];
                vf[p*2+1][0] = r[2]; vf[p*2+1][1] = r[3];
            }
            #pragma unroll
            for (int tn2 = 0; tn2 < 8; tn2++)
                mma_f16(oacc[tn2], ah, vf[tn2]);
        }
        __syncthreads();
    }

    // ---- write partials ----
    float* po = z ? g_po1 : g_po0;
    float* ml = z ? g_ml1 : g_ml0;
    #pragma unroll
    for (int tn2 = 0; tn2 < 8; tn2++) {
        int col = h * EDIM + tn2 * 8 + fkc;
        *(float2*)&po[(size_t)(b * SEQ + rA) * D_MODEL + col] = make_float2(oacc[tn2][0], oacc[tn2][1]);
        *(float2*)&po[(size_t)(b * SEQ + rB) * D_MODEL + col] = make_float2(oacc[tn2][2], oacc[tn2][3]);
    }
    if ((lane & 3) == 0) {
        *(float2*)&ml[(size_t)(bh * SEQ + rA) * 2] = make_float2(m0, l0);
        *(float2*)&ml[(size_t)(bh * SEQ + rB) * 2] = make_float2(m1, l1);
    }
}

// merge split-KV partials -> fp16 attn output
__global__ __launch_bounds__(256) void merge_k()
{
    const int idx2 = (blockIdx.x * 256 + threadIdx.x) * 2;
    const int r = idx2 >> 9;
    const int d = idx2 & 511;
    const int bh = ((r >> 11) << 3) | (d >> 6);
    const int srow = r & (SEQ - 1);
    float2 ml0 = *(float2*)&g_ml0[(size_t)(bh * SEQ + srow) * 2];
    float2 ml1 = *(float2*)&g_ml1[(size_t)(bh * SEQ + srow) * 2];
    float M = fmaxf(ml0.x, ml1.x);
    float w0 = __expf(ml0.x - M), w1 = __expf(ml1.x - M);
    float inv = 1.0f / (ml0.y * w0 + ml1.y * w1);
    float2 p0 = *(float2*)&g_po0[idx2];
    float2 p1 = *(float2*)&g_po1[idx2];
    float v0 = (p0.x * w0 + p1.x * w1) * inv;
    float v1 = (p0.y * w0 + p1.y * w1) * inv;
    *(uint32_t*)&s_attn_h[idx2] = hpack2(v0, v1);
}

// ---------------- LayerNorm (+ optional fp16 output) ----------------
__global__ __launch_bounds__(128) void ln_k(
    const float* __restrict__ x, const float* __restrict__ g,
    const float* __restrict__ bb, float* __restrict__ y,
    uint16_t* __restrict__ yh)
{
    const int row = blockIdx.x;
    const float* p = x + (size_t)row * D_MODEL;
    const int tid = threadIdx.x;
    float4 v = *(const float4*)(p + tid * 4);
    float s = v.x + v.y + v.z + v.w;
    __shared__ float sh[4];
    #pragma unroll
    for (int o = 16; o > 0; o >>= 1) s += __shfl_xor_sync(~0u, s, o);
    if ((tid & 31) == 0) sh[tid >> 5] = s;
    __syncthreads();
    s = sh[0] + sh[1] + sh[2] + sh[3];
    const float mean = s * (1.0f / (float)D_MODEL);
    float vs = (v.x - mean) * (v.x - mean) + (v.y - mean) * (v.y - mean)
             + (v.z - mean) * (v.z - mean) + (v.w - mean) * (v.w - mean);
    #pragma unroll
    for (int o = 16; o > 0; o >>= 1) vs += __shfl_xor_sync(~0u, vs, o);
    __syncthreads();
    if ((tid & 31) == 0) sh[tid >> 5] = vs;
    __syncthreads();
    vs = sh[0] + sh[1] + sh[2] + sh[3];
    const float rstd = rsqrtf(vs * (1.0f / (float)D_MODEL) + 1e-5f);
    const int col = tid * 4;
    const float4 gg = *(const float4*)(g + col);
    const float4 bbv = *(const float4*)(bb + col);
    float4 out;
    out.x = (v.x - mean) * rstd * gg.x + bbv.x;
    out.y = (v.y - mean) * rstd * gg.y + bbv.y;
    out.z = (v.z - mean) * rstd * gg.z + bbv.z;
    out.w = (v.w - mean) * rstd * gg.w + bbv.w;
    *(float4*)(y + (size_t)row * D_MODEL + col) = out;
    if (yh != nullptr) {
        size_t o = (size_t)row * D_MODEL + col;
        *(uint32_t*)&yh[o]     = hpack2(out.x, out.y);
        *(uint32_t*)&yh[o + 2] = hpack2(out.z, out.w);
    }
}

// ---------------- orchestration ----------------
extern "C" void kernel_launch(void* const* d_in, const int* in_sizes, int n_in,
                              void* d_out, int out_size)
{
    const float* x_in  = (const float*)d_in[0];
    const float* tau   = (const float*)d_in[1];
    const float* delta = (const float*)d_in[2];
    const float* Wq = (const float*)d_in[4];
    const float* bq = (const float*)d_in[5];
    const float* Wk = (const float*)d_in[6];
    const float* bk = (const float*)d_in[7];
    const float* Wv = (const float*)d_in[8];
    const float* bv = (const float*)d_in[9];
    const float* Wo = (const float*)d_in[10];
    const float* bo = (const float*)d_in[11];
    const float* W1 = (const float*)d_in[12];
    const float* b1 = (const float*)d_in[13];
    const float* W2 = (const float*)d_in[14];
    const float* b2 = (const float*)d_in[15];
    const float* ln1g = (const float*)d_in[16];
    const float* ln1b = (const float*)d_in[17];
    const float* ln2g = (const float*)d_in[18];
    const float* ln2b = (const float*)d_in[19];
    const float* lnfg = (const float*)d_in[20];
    const float* lnfb = (const float*)d_in[21];

    float *gx, *gxb, *go;
    cudaGetSymbolAddress((void**)&gx,  g_x);
    cudaGetSymbolAddress((void**)&gxb, g_xb);
    cudaGetSymbolAddress((void**)&go,  g_o);

    uint16_t *axh, *axbh, *ahh, *aath;
    cudaGetSymbolAddress((void**)&axh,  s_x_h);
    cudaGetSymbolAddress((void**)&axbh, s_xb_h);
    cudaGetSymbolAddress((void**)&ahh,  s_h_h);
    cudaGetSymbolAddress((void**)&aath, s_attn_h);

    uint16_t *wo_h, *w1_h, *w2_h;
    cudaGetSymbolAddress((void**)&wo_h, s_Wo_h);
    cudaGetSymbolAddress((void**)&w1_h, s_W1_h);
    cudaGetSymbolAddress((void**)&w2_h, s_W2_h);

    const int SM4 = 3 * (10240 + 4 * 2560);   // 61440
    const int SM2 = 3 * (10240 + 2 * 2560);   // 46080

    cudaFuncSetAttribute(gemm_split_t<4>, cudaFuncAttributeMaxDynamicSharedMemorySize, SM4);
    cudaFuncSetAttribute(gemm_split_t<2>, cudaFuncAttributeMaxDynamicSharedMemorySize, SM2);
    cudaFuncSetAttribute(gemm_qkv,        cudaFuncAttributeMaxDynamicSharedMemorySize, SM4);
    cudaFuncSetAttribute(flash_split,     cudaFuncAttributeMaxDynamicSharedMemorySize, F_SMEM);

    transp_split<<<dim3(64, 64, 12), 256>>>(Wq, Wk, Wv, Wo, W1, W2);
    split_x<<<ROWS * D_MODEL / 1024, 256>>>(x_in);

    const dim3 gQKV(D_MODEL / 128, ROWS / 128, 3);     // (4, 32, 3)
    const dim3 gProj64(D_MODEL / 64, ROWS / 128);      // (8, 32)
    const dim3 gFF1(D_FF / 128, ROWS / 128);           // (16, 32)
    const dim3 gFlash(2 * SEQ / 128, BH);              // (32, 16)
    const dim3 gVT(SEQ / 32, BH);                      // (64, 16)

    for (int l = 0; l < 2; l++) {
        const int wOff   = l * D_MODEL * D_MODEL;
        const int w1Off  = l * D_MODEL * D_FF;
        const size_t bOff  = (size_t)l * D_MODEL;
        const size_t b1Off = (size_t)l * D_FF;

        gemm_qkv<<<gQKV, 256, SM4>>>(bq + bOff, bk + bOff, bv + bOff, wOff);
        vtransp<<<gVT, 256>>>();
        flash_split<<<gFlash, 256, F_SMEM>>>(tau, delta);
        merge_k<<<ROWS * D_MODEL / 512, 256>>>();

        gemm_split_t<2><<<gProj64, 256, SM2>>>(aath, wo_h + wOff,
                                               bo + bOff, gx, gx, nullptr,
                                               D_MODEL, D_MODEL, 1);
        ln_k<<<ROWS, 128>>>(gx, ln1g + bOff, ln1b + bOff, gxb, axbh);

        gemm_split_t<4><<<gFF1, 256, SM4>>>(axbh, w1_h + w1Off,
                                            b1 + b1Off, nullptr, nullptr, ahh,
                                            D_FF, D_MODEL, 2);
        gemm_split_t<2><<<gProj64, 256, SM2>>>(ahh, w2_h + w1Off,
                                               b2 + bOff, gxb, go, nullptr,
                                               D_MODEL, D_FF, 1);
        ln_k<<<ROWS, 128>>>(go, ln2g + bOff, ln2b + bOff, gx, axh);
    }
    ln_k<<<ROWS, 128>>>(gx, lnfg, lnfb, (float*)d_out, nullptr);
}

// round 10
// speedup vs baseline: 2.3461x; 1.0038x over previous
#include <cuda_runtime.h>
#include <cuda_fp16.h>
#include <math.h>
#include <stdint.h>

#define D_MODEL 512
#define D_FF 2048
#define BATCH 2
#define SEQ 2048
#define NHEADS 8
#define EDIM 64
#define ROWS (BATCH*SEQ)
#define BH (BATCH*NHEADS)
#define GELU_CF 0.7978845608028654f
#define WSZ  (2*D_MODEL*D_MODEL)
#define W1SZ (2*D_MODEL*D_FF)

// ---------------- f32 scratch ----------------
__device__ float g_x[ROWS*D_MODEL];
__device__ float g_xb[ROWS*D_MODEL];
__device__ float g_o[ROWS*D_MODEL];
__device__ float g_po0[ROWS*D_MODEL];
__device__ float g_po1[ROWS*D_MODEL];
__device__ float g_ml0[BH*SEQ*2];
__device__ float g_ml1[BH*SEQ*2];

// ---------------- fp16 TRANSPOSED weights ([layer][N][K]) ----------------
__device__ uint16_t s_Wq_h[WSZ];
__device__ uint16_t s_Wk_h[WSZ];
__device__ uint16_t s_Wv_h[WSZ];
__device__ uint16_t s_Wo_h[WSZ];
__device__ uint16_t s_W1_h[W1SZ];
__device__ uint16_t s_W2_h[W1SZ];

// ---------------- fp16 activations ----------------
__device__ uint16_t s_x_h[ROWS*D_MODEL];
__device__ uint16_t s_xb_h[ROWS*D_MODEL];
__device__ uint16_t s_q_h[ROWS*D_MODEL];
__device__ uint16_t s_k_h[ROWS*D_MODEL];
__device__ uint16_t s_v_h[ROWS*D_MODEL];
__device__ uint16_t s_vT_h[ROWS*D_MODEL];   // [bh][e][tok]
__device__ uint16_t s_attn_h[ROWS*D_MODEL];
__device__ uint16_t s_h_h[ROWS*D_FF];

// =======================================================================
// helpers
// =======================================================================
__device__ __forceinline__ uint32_t hpack2(float x0, float x1) {
    __half2 hh = __floats2half2_rn(x0, x1);
    return *reinterpret_cast<uint32_t*>(&hh);
}

__device__ __forceinline__ void mma_f16(float* c, const uint32_t* a, const uint32_t* b) {
    asm volatile(
        "mma.sync.aligned.m16n8k16.row.col.f32.f16.f16.f32 "
        "{%0,%1,%2,%3}, {%4,%5,%6,%7}, {%8,%9}, {%0,%1,%2,%3};"
        : "+f"(c[0]), "+f"(c[1]), "+f"(c[2]), "+f"(c[3])
        : "r"(a[0]), "r"(a[1]), "r"(a[2]), "r"(a[3]), "r"(b[0]), "r"(b[1]));
}

__device__ __forceinline__ void ldsm_x4(uint32_t* r, uint32_t addr) {
    asm volatile("ldmatrix.sync.aligned.m8n8.x4.shared.b16 {%0,%1,%2,%3}, [%4];"
        : "=r"(r[0]), "=r"(r[1]), "=r"(r[2]), "=r"(r[3]) : "r"(addr));
}

__device__ __forceinline__ uint32_t smem_u32(const void* p) {
    uint32_t a;
    asm("{ .reg .u64 t; cvta.to.shared.u64 t, %1; cvt.u32.u64 %0, t; }"
        : "=r"(a) : "l"(p));
    return a;
}

__device__ __forceinline__ void cp16(uint32_t dst, const void* src) {
    asm volatile("cp.async.cg.shared.global [%0], [%1], 16;\n" :: "r"(dst), "l"(src));
}
__device__ __forceinline__ void cp_commit() {
    asm volatile("cp.async.commit_group;\n" ::: "memory");
}
__device__ __forceinline__ void cp_wait2() {
    asm volatile("cp.async.wait_group 2;\n" ::: "memory");
}
__device__ __forceinline__ void cp_wait1() {
    asm volatile("cp.async.wait_group 1;\n" ::: "memory");
}
__device__ __forceinline__ void cp_wait0() {
    asm volatile("cp.async.wait_group 0;\n" ::: "memory");
}

// =======================================================================
// prologue
// =======================================================================
__global__ __launch_bounds__(256) void transp_split(
    const float* __restrict__ Wq, const float* __restrict__ Wk,
    const float* __restrict__ Wv, const float* __restrict__ Wo,
    const float* __restrict__ W1, const float* __restrict__ W2)
{
    const int w = blockIdx.z >> 1, layer = blockIdx.z & 1;
    const float* src; uint16_t* dh; int K, N;
    switch (w) {
        case 0: src = Wq; dh = s_Wq_h; K = 512;  N = 512;  break;
        case 1: src = Wk; dh = s_Wk_h; K = 512;  N = 512;  break;
        case 2: src = Wv; dh = s_Wv_h; K = 512;  N = 512;  break;
        case 3: src = Wo; dh = s_Wo_h; K = 512;  N = 512;  break;
        case 4: src = W1; dh = s_W1_h; K = 512;  N = 2048; break;
        default: src = W2; dh = s_W2_h; K = 2048; N = 512; break;
    }
    const int k0 = blockIdx.x * 32, n0 = blockIdx.y * 32;
    if (k0 >= K || n0 >= N) return;
    src += (size_t)layer * K * N;
    dh  += (size_t)layer * K * N;

    __shared__ float t[32][33];
    const int tid = threadIdx.x;
    const int tx = tid & 31, ty = tid >> 5;
    #pragma unroll
    for (int i = 0; i < 4; i++) {
        int k = ty + i * 8;
        t[k][tx] = src[(size_t)(k0 + k) * N + n0 + tx];
    }
    __syncthreads();
    const int n = tid >> 3, kq = tid & 7;
    float a0 = t[kq*4+0][n], a1 = t[kq*4+1][n], a2 = t[kq*4+2][n], a3 = t[kq*4+3][n];
    size_t o = (size_t)(n0 + n) * K + k0 + kq * 4;
    *(uint32_t*)&dh[o]     = hpack2(a0, a1);
    *(uint32_t*)&dh[o + 2] = hpack2(a2, a3);
}

__global__ __launch_bounds__(256) void split_x(const float* __restrict__ x)
{
    int idx = (blockIdx.x * 256 + threadIdx.x) * 4;
    float4 v = *(const float4*)(x + idx);
    *(float4*)(g_x + idx) = v;
    *(uint32_t*)&s_x_h[idx]     = hpack2(v.x, v.y);
    *(uint32_t*)&s_x_h[idx + 2] = hpack2(v.z, v.w);
}

// V transpose: s_v_h [tok][h*64+e] -> s_vT_h [bh][e][tok]
__global__ __launch_bounds__(256) void vtransp()
{
    __shared__ uint16_t tt[32][66];
    const int bh = blockIdx.y;
    const int b = bh >> 3, h = bh & 7;
    const int tok0 = blockIdx.x * 32;
    const int tid = threadIdx.x;
    #pragma unroll
    for (int i = 0; i < 4; i++) {
        int idx = tid + i * 256;
        int r = idx >> 5, c = idx & 31;
        uint32_t v = *(const uint32_t*)&s_v_h[(size_t)(b * SEQ + tok0 + r) * D_MODEL + h * 64 + c * 2];
        *(uint32_t*)&tt[r][c * 2] = v;
    }
    __syncthreads();
    #pragma unroll
    for (int i = 0; i < 4; i++) {
        int idx = tid + i * 256;
        int e = idx >> 4, t2 = idx & 15;
        uint32_t v = (uint32_t)tt[t2 * 2][e] | ((uint32_t)tt[t2 * 2 + 1][e] << 16);
        *(uint32_t*)&s_vT_h[((size_t)bh * EDIM + e) * SEQ + tok0 + t2 * 2] = v;
    }
}

// =======================================================================
// GEMM: pure fp16, ldmatrix frags. A [M][K], B (transposed weights) [N][K].
// Block tile 128 x (TN*32). 256 thr. 4-stage cp.async pipeline, single sync.
// Stage: A(10240) + B(TN*2560)
// =======================================================================
#define A_PITCH 40

// epi: 0 = bias -> fp16 out; 1 = bias + add -> f32 out; 2 = bias + gelu -> fp16 out
template<int TN>
__device__ __forceinline__ void gemm_body(
    const uint16_t* __restrict__ Ah, const uint16_t* __restrict__ Bh,
    const float* __restrict__ bias, const float* __restrict__ add,
    float* __restrict__ Cf, uint16_t* __restrict__ Ch,
    int N, int K, int epi, int bm, int bn, char* sm)
{
    constexpr int STAGE = 10240 + TN * 2560;
    constexpr int NP = TN / 2;
    const int tid = threadIdx.x;
    const int wid = tid >> 5;
    const int lane = tid & 31;
    const int wm = wid & 1;
    const int wn = wid >> 1;
    const int fr = lane >> 2;
    const int fkc = (lane & 3) * 2;
    const int mi = lane >> 3, ri = lane & 7;
    const uint32_t sb = smem_u32(sm);

    int aoff[4];
    #pragma unroll
    for (int tm = 0; tm < 4; tm++)
        aoff[tm] = ((wm * 64 + tm * 16 + (mi & 1) * 8 + ri) * A_PITCH + (mi >> 1) * 8) * 2;
    int boff[NP];
    #pragma unroll
    for (int p = 0; p < NP; p++)
        boff[p] = ((wn * (TN * 8) + (p * 2 + (mi >> 1)) * 8 + ri) * A_PITCH + (mi & 1) * 8) * 2;

    float acc[4][TN][4];
    #pragma unroll
    for (int tm = 0; tm < 4; tm++)
        #pragma unroll
        for (int tn = 0; tn < TN; tn++)
            #pragma unroll
            for (int i = 0; i < 4; i++) acc[tm][tn][i] = 0.f;

    const int nChunks = K >> 5;

    auto issue = [&](int st, int kt) {
        uint32_t base = sb + st * STAGE;
        #pragma unroll
        for (int t = 0; t < 2 + NP; t++) {
            int idx = tid + t * 256;
            if (idx < 512) {
                int row = idx >> 2, c4 = idx & 3;
                cp16(base + row * 80 + c4 * 16, Ah + (size_t)(bm + row) * K + kt + c4 * 8);
            } else {
                int j = idx - 512;
                int row = j >> 2, c4 = j & 3;
                cp16(base + 10240 + row * 80 + c4 * 16, Bh + (size_t)(bn + row) * K + kt + c4 * 8);
            }
        }
        cp_commit();
    };

    issue(0, 0);
    if (nChunks > 1) issue(1, 32);

    for (int chunk = 0; chunk < nChunks; chunk++) {
        if (chunk + 2 < nChunks) {
            issue((chunk + 2) & 3, (chunk + 2) << 5);
            cp_wait2();
        } else if (chunk + 1 < nChunks) {
            cp_wait1();
        } else {
            cp_wait0();
        }
        __syncthreads();

        const uint32_t stgA = sb + (chunk & 3) * STAGE;
        const uint32_t stgB = stgA + 10240;

        #pragma unroll
        for (int ks = 0; ks < 2; ks++) {
            const int K0b = ks * 32;
            uint32_t ah[4][4];
            #pragma unroll
            for (int tm = 0; tm < 4; tm++)
                ldsm_x4(ah[tm], stgA + aoff[tm] + K0b);
            uint32_t bhf[TN][2];
            #pragma unroll
            for (int p = 0; p < NP; p++) {
                uint32_t r[4];
                ldsm_x4(r, stgB + boff[p] + K0b);
                bhf[p*2][0] = r[0]; bhf[p*2][1] = r[1];
                bhf[p*2+1][0] = r[2]; bhf[p*2+1][1] = r[3];
            }
            #pragma unroll
            for (int tm = 0; tm < 4; tm++)
                #pragma unroll
                for (int tn = 0; tn < TN; tn++)
                    mma_f16(acc[tm][tn], ah[tm], bhf[tn]);
        }
        // no trailing sync: 4-stage ring + write-ahead-2 + skew<=1 is race-free
    }

    #pragma unroll
    for (int tm = 0; tm < 4; tm++) {
        #pragma unroll
        for (int tn = 0; tn < TN; tn++) {
            int row0 = bm + wm * 64 + tm * 16 + fr;
            int col = bn + wn * (TN * 8) + tn * 8 + fkc;
            float b0 = bias[col], b1 = bias[col + 1];
            #pragma unroll
            for (int half = 0; half < 2; half++) {
                int row = row0 + half * 8;
                float v0 = acc[tm][tn][half * 2 + 0] + b0;
                float v1 = acc[tm][tn][half * 2 + 1] + b1;
                if (epi == 1) {
                    const float* ap = add + (size_t)row * N + col;
                    v0 += ap[0]; v1 += ap[1];
                    *(float2*)(Cf + (size_t)row * N + col) = make_float2(v0, v1);
                } else {
                    if (epi == 2) {
                        float u = v0;
                        v0 = 0.5f * u * (1.0f + tanhf(GELU_CF * (u + 0.044715f * u * u * u)));
                        u = v1;
                        v1 = 0.5f * u * (1.0f + tanhf(GELU_CF * (u + 0.044715f * u * u * u)));
                    }
                    *(uint32_t*)&Ch[(size_t)row * N + col] = hpack2(v0, v1);
                }
            }
        }
    }
}

template<int TN>
__global__ __launch_bounds__(256, 2) void gemm_split_t(
    const uint16_t* __restrict__ Ah, const uint16_t* __restrict__ Bh,
    const float* __restrict__ bias, const float* __restrict__ add,
    float* __restrict__ Cf, uint16_t* __restrict__ Ch,
    int N, int K, int epi)
{
    extern __shared__ char sm[];
    gemm_body<TN>(Ah, Bh, bias, add, Cf, Ch, N, K, epi,
                  blockIdx.y * 128, blockIdx.x * (TN * 32), sm);
}

__global__ __launch_bounds__(256, 2) void gemm_qkv(
    const float* __restrict__ bq, const float* __restrict__ bk,
    const float* __restrict__ bv, int lw)
{
    extern __shared__ char sm[];
    const int z = blockIdx.z;
    const uint16_t* Bh;
    const float* bias;
    uint16_t* Ch;
    if (z == 0)      { Bh = s_Wq_h + lw; bias = bq; Ch = s_q_h; }
    else if (z == 1) { Bh = s_Wk_h + lw; bias = bk; Ch = s_k_h; }
    else             { Bh = s_Wv_h + lw; bias = bv; Ch = s_v_h; }
    gemm_body<2>(s_x_h, Bh, bias, nullptr, nullptr, Ch,
                 D_MODEL, D_MODEL, 0, blockIdx.y * 128, blockIdx.x * 64, sm);
}

// =======================================================================
// Flash attention, 2-way split-KV, pure fp16, ldmatrix frags.
// 4-stage cp.async pipeline (write-ahead 2), single sync per tile.
// Stage: Kh(9216) VTh(9216) = 18432; 4 stages.
// =======================================================================
#define KP 72
#define F_STAGE 18432
#define F_SMEM (4*F_STAGE)

__global__ __launch_bounds__(256, 2) void flash_split(
    const float* __restrict__ tau, const float* __restrict__ delta)
{
    extern __shared__ char sm[];
    const uint32_t sb = smem_u32(sm);
    const int tid = threadIdx.x;
    const int wid = tid >> 5;
    const int lane = tid & 31;
    const int fr = lane >> 2;
    const int fkc = (lane & 3) * 2;
    const int mi = lane >> 3, ri = lane & 7;

    const int nLt = gridDim.x >> 1;
    const int lt = nLt - 1 - (blockIdx.x >> 1);
    const int z = blockIdx.x & 1;
    const int bh = blockIdx.y;
    const int b = bh >> 3, h = bh & 7;
    const int qrow0 = lt * 128;
    const int rA = qrow0 + wid * 16 + fr;
    const int rB = rA + 8;

    int koff[4];
    #pragma unroll
    for (int p = 0; p < 4; p++)
        koff[p] = (((p * 2 + (mi >> 1)) * 8 + ri) * KP + (mi & 1) * 8) * 2;

    uint32_t qh[4][4];
    #pragma unroll
    for (int ks = 0; ks < 4; ks++) {
        int e0 = ks * 16 + fkc;
        size_t oA = (size_t)(b * SEQ + rA) * D_MODEL + h * EDIM + e0;
        size_t oB = (size_t)(b * SEQ + rB) * D_MODEL + h * EDIM + e0;
        qh[ks][0] = *(const uint32_t*)&s_q_h[oA];
        qh[ks][1] = *(const uint32_t*)&s_q_h[oB];
        qh[ks][2] = *(const uint32_t*)&s_q_h[oA + 8];
        qh[ks][3] = *(const uint32_t*)&s_q_h[oB + 8];
    }

    float oacc[8][4];
    #pragma unroll
    for (int t = 0; t < 8; t++)
        #pragma unroll
        for (int i = 0; i < 4; i++) oacc[t][i] = 0.f;
    float m0 = -3.0e38f, m1 = -3.0e38f;
    float l0 = 0.f, l1 = 0.f;
    const float sct = 0.125f * __ldg(&tau[b]);

    const int stStart = z * (lt + 1);
    const int nTiles = lt + 1;

    auto issue = [&](int stage, int key_base) {
        uint32_t base = sb + stage * F_STAGE;
        {
            int row = tid >> 2, c4 = tid & 3;
            size_t gk = (size_t)(b * SEQ + key_base + row) * D_MODEL + h * EDIM + c4 * 16;
            uint32_t dk = base + row * 144 + c4 * 32;
            cp16(dk, s_k_h + gk);
            cp16(dk + 16, s_k_h + gk + 8);
            size_t gv = ((size_t)bh * EDIM + row) * SEQ + key_base + c4 * 16;
            uint32_t dv = base + 9216 + row * 144 + c4 * 32;
            cp16(dv, s_vT_h + gv);
            cp16(dv + 16, s_vT_h + gv + 8);
        }
        cp_commit();
    };

    issue(0, stStart * 64);
    if (nTiles > 1) issue(1, (stStart + 1) * 64);

    for (int it = 0; it < nTiles; it++) {
        const int key_base = (stStart + it) * 64;
        if (it + 2 < nTiles) {
            issue((it + 2) & 3, (stStart + it + 2) * 64);
            cp_wait2();
        } else if (it + 1 < nTiles) {
            cp_wait1();
        } else {
            cp_wait0();
        }
        __syncthreads();

        const uint32_t stgK = sb + (it & 3) * F_STAGE;
        const uint32_t stgV = stgK + 9216;

        // ---- S = Q K^T ----
        float s[8][4];
        #pragma unroll
        for (int t = 0; t < 8; t++)
            #pragma unroll
            for (int i = 0; i < 4; i++) s[t][i] = 0.f;

        #pragma unroll
        for (int ks = 0; ks < 4; ks++) {
            uint32_t bf[8][2];
            #pragma unroll
            for (int p = 0; p < 4; p++) {
                uint32_t r[4];
                ldsm_x4(r, stgK + koff[p] + ks * 32);
                bf[p*2][0] = r[0]; bf[p*2][1] = r[1];
                bf[p*2+1][0] = r[2]; bf[p*2+1][1] = r[3];
            }
            #pragma unroll
            for (int tn = 0; tn < 8; tn++)
                mma_f16(s[tn], qh[ks], bf[tn]);
        }

        // ---- scale + bias + mask ----
        const bool masked = (key_base + 63) > qrow0;
        #pragma unroll
        for (int tn = 0; tn < 8; tn++) {
            int key = key_base + tn * 8 + fkc;
            float2 dd = *(const float2*)(delta + b * SEQ + key);
            float d0 = 0.125f * dd.x, d1 = 0.125f * dd.y;
            s[tn][0] = fmaf(s[tn][0], sct, d0);
            s[tn][1] = fmaf(s[tn][1], sct, d1);
            s[tn][2] = fmaf(s[tn][2], sct, d0);
            s[tn][3] = fmaf(s[tn][3], sct, d1);
            if (masked) {
                if (key     > rA) s[tn][0] = -1e30f;
                if (key + 1 > rA) s[tn][1] = -1e30f;
                if (key     > rB) s[tn][2] = -1e30f;
                if (key + 1 > rB) s[tn][3] = -1e30f;
            }
        }

        // ---- online softmax ----
        float r0 = -3.0e38f, r1 = -3.0e38f;
        #pragma unroll
        for (int tn = 0; tn < 8; tn++) {
            r0 = fmaxf(r0, fmaxf(s[tn][0], s[tn][1]));
            r1 = fmaxf(r1, fmaxf(s[tn][2], s[tn][3]));
        }
        r0 = fmaxf(r0, __shfl_xor_sync(~0u, r0, 1));
        r0 = fmaxf(r0, __shfl_xor_sync(~0u, r0, 2));
        r1 = fmaxf(r1, __shfl_xor_sync(~0u, r1, 1));
        r1 = fmaxf(r1, __shfl_xor_sync(~0u, r1, 2));
        float mn0 = fmaxf(m0, r0), mn1 = fmaxf(m1, r1);
        float sc0 = __expf(m0 - mn0), sc1 = __expf(m1 - mn1);
        float sum0 = 0.f, sum1 = 0.f;
        #pragma unroll
        for (int tn = 0; tn < 8; tn++) {
            s[tn][0] = __expf(s[tn][0] - mn0); sum0 += s[tn][0];
            s[tn][1] = __expf(s[tn][1] - mn0); sum0 += s[tn][1];
            s[tn][2] = __expf(s[tn][2] - mn1); sum1 += s[tn][2];
            s[tn][3] = __expf(s[tn][3] - mn1); sum1 += s[tn][3];
        }
        sum0 += __shfl_xor_sync(~0u, sum0, 1);
        sum0 += __shfl_xor_sync(~0u, sum0, 2);
        sum1 += __shfl_xor_sync(~0u, sum1, 1);
        sum1 += __shfl_xor_sync(~0u, sum1, 2);
        l0 = l0 * sc0 + sum0; m0 = mn0;
        l1 = l1 * sc1 + sum1; m1 = mn1;
        #pragma unroll
        for (int t = 0; t < 8; t++) {
            oacc[t][0] *= sc0; oacc[t][1] *= sc0;
            oacc[t][2] *= sc1; oacc[t][3] *= sc1;
        }

        // ---- O += P V ----
        #pragma unroll
        for (int kc = 0; kc < 4; kc++) {
            uint32_t ah[4];
            ah[0] = hpack2(s[2*kc][0],   s[2*kc][1]);
            ah[1] = hpack2(s[2*kc][2],   s[2*kc][3]);
            ah[2] = hpack2(s[2*kc+1][0], s[2*kc+1][1]);
            ah[3] = hpack2(s[2*kc+1][2], s[2*kc+1][3]);
            uint32_t vf[8][2];
            #pragma unroll
            for (int p = 0; p < 4; p++) {
                uint32_t r[4];
                ldsm_x4(r, stgV + koff[p] + kc * 32);
                vf[p*2][0] = r[0]; vf[p*2][1] = r[1];
                vf[p*2+1][0] = r[2]; vf[p*2+1][1] = r[3];
            }
            #pragma unroll
            for (int tn2 = 0; tn2 < 8; tn2++)
                mma_f16(oacc[tn2], ah, vf[tn2]);
        }
        // no trailing sync (4-stage ring, write-ahead 2)
    }

    // ---- write partials ----
    float* po = z ? g_po1 : g_po0;
    float* ml = z ? g_ml1 : g_ml0;
    #pragma unroll
    for (int tn2 = 0; tn2 < 8; tn2++) {
        int col = h * EDIM + tn2 * 8 + fkc;
        *(float2*)&po[(size_t)(b * SEQ + rA) * D_MODEL + col] = make_float2(oacc[tn2][0], oacc[tn2][1]);
        *(float2*)&po[(size_t)(b * SEQ + rB) * D_MODEL + col] = make_float2(oacc[tn2][2], oacc[tn2][3]);
    }
    if ((lane & 3) == 0) {
        *(float2*)&ml[(size_t)(bh * SEQ + rA) * 2] = make_float2(m0, l0);
        *(float2*)&ml[(size_t)(bh * SEQ + rB) * 2] = make_float2(m1, l1);
    }
}

// merge split-KV partials -> fp16 attn output
__global__ __launch_bounds__(256) void merge_k()
{
    const int idx2 = (blockIdx.x * 256 + threadIdx.x) * 2;
    const int r = idx2 >> 9;
    const int d = idx2 & 511;
    const int bh = ((r >> 11) << 3) | (d >> 6);
    const int srow = r & (SEQ - 1);
    float2 ml0 = *(float2*)&g_ml0[(size_t)(bh * SEQ + srow) * 2];
    float2 ml1 = *(float2*)&g_ml1[(size_t)(bh * SEQ + srow) * 2];
    float M = fmaxf(ml0.x, ml1.x);
    float w0 = __expf(ml0.x - M), w1 = __expf(ml1.x - M);
    float inv = 1.0f / (ml0.y * w0 + ml1.y * w1);
    float2 p0 = *(float2*)&g_po0[idx2];
    float2 p1 = *(float2*)&g_po1[idx2];
    float v0 = (p0.x * w0 + p1.x * w1) * inv;
    float v1 = (p0.y * w0 + p1.y * w1) * inv;
    *(uint32_t*)&s_attn_h[idx2] = hpack2(v0, v1);
}

// ---------------- LayerNorm: 2 rows per block, 256 threads ----------------
__global__ __launch_bounds__(256) void ln_k(
    const float* __restrict__ x, const float* __restrict__ g,
    const float* __restrict__ bb, float* __restrict__ y,
    uint16_t* __restrict__ yh)
{
    const int sub = threadIdx.x >> 7;            // 0/1: which row
    const int tid = threadIdx.x & 127;
    const int row = blockIdx.x * 2 + sub;
    const float* p = x + (size_t)row * D_MODEL;
    float4 v = *(const float4*)(p + tid * 4);
    float s = v.x + v.y + v.z + v.w;
    __shared__ float sh[8];
    #pragma unroll
    for (int o = 16; o > 0; o >>= 1) s += __shfl_xor_sync(~0u, s, o);
    if ((threadIdx.x & 31) == 0) sh[threadIdx.x >> 5] = s;
    __syncthreads();
    const int base4 = sub * 4;
    s = sh[base4] + sh[base4+1] + sh[base4+2] + sh[base4+3];
    const float mean = s * (1.0f / (float)D_MODEL);
    float vs = (v.x - mean) * (v.x - mean) + (v.y - mean) * (v.y - mean)
             + (v.z - mean) * (v.z - mean) + (v.w - mean) * (v.w - mean);
    #pragma unroll
    for (int o = 16; o > 0; o >>= 1) vs += __shfl_xor_sync(~0u, vs, o);
    __syncthreads();
    if ((threadIdx.x & 31) == 0) sh[threadIdx.x >> 5] = vs;
    __syncthreads();
    vs = sh[base4] + sh[base4+1] + sh[base4+2] + sh[base4+3];
    const float rstd = rsqrtf(vs * (1.0f / (float)D_MODEL) + 1e-5f);
    const int col = tid * 4;
    const float4 gg = *(const float4*)(g + col);
    const float4 bbv = *(const float4*)(bb + col);
    float4 out;
    out.x = (v.x - mean) * rstd * gg.x + bbv.x;
    out.y = (v.y - mean) * rstd * gg.y + bbv.y;
    out.z = (v.z - mean) * rstd * gg.z + bbv.z;
    out.w = (v.w - mean) * rstd * gg.w + bbv.w;
    *(float4*)(y + (size_t)row * D_MODEL + col) = out;
    if (yh != nullptr) {
        size_t o = (size_t)row * D_MODEL + col;
        *(uint32_t*)&yh[o]     = hpack2(out.x, out.y);
        *(uint32_t*)&yh[o + 2] = hpack2(out.z, out.w);
    }
}

// ---------------- orchestration ----------------
extern "C" void kernel_launch(void* const* d_in, const int* in_sizes, int n_in,
                              void* d_out, int out_size)
{
    const float* x_in  = (const float*)d_in[0];
    const float* tau   = (const float*)d_in[1];
    const float* delta = (const float*)d_in[2];
    const float* Wq = (const float*)d_in[4];
    const float* bq = (const float*)d_in[5];
    const float* Wk = (const float*)d_in[6];
    const float* bk = (const float*)d_in[7];
    const float* Wv = (const float*)d_in[8];
    const float* bv = (const float*)d_in[9];
    const float* Wo = (const float*)d_in[10];
    const float* bo = (const float*)d_in[11];
    const float* W1 = (const float*)d_in[12];
    const float* b1 = (const float*)d_in[13];
    const float* W2 = (const float*)d_in[14];
    const float* b2 = (const float*)d_in[15];
    const float* ln1g = (const float*)d_in[16];
    const float* ln1b = (const float*)d_in[17];
    const float* ln2g = (const float*)d_in[18];
    const float* ln2b = (const float*)d_in[19];
    const float* lnfg = (const float*)d_in[20];
    const float* lnfb = (const float*)d_in[21];

    float *gx, *gxb, *go;
    cudaGetSymbolAddress((void**)&gx,  g_x);
    cudaGetSymbolAddress((void**)&gxb, g_xb);
    cudaGetSymbolAddress((void**)&go,  g_o);

    uint16_t *axh, *axbh, *ahh, *aath;
    cudaGetSymbolAddress((void**)&axh,  s_x_h);
    cudaGetSymbolAddress((void**)&axbh, s_xb_h);
    cudaGetSymbolAddress((void**)&ahh,  s_h_h);
    cudaGetSymbolAddress((void**)&aath, s_attn_h);

    uint16_t *wo_h, *w1_h, *w2_h;
    cudaGetSymbolAddress((void**)&wo_h, s_Wo_h);
    cudaGetSymbolAddress((void**)&w1_h, s_W1_h);
    cudaGetSymbolAddress((void**)&w2_h, s_W2_h);

    const int SM4 = 4 * (10240 + 4 * 2560);   // 81920
    const int SM2 = 4 * (10240 + 2 * 2560);   // 61440

    cudaFuncSetAttribute(gemm_split_t<4>, cudaFuncAttributeMaxDynamicSharedMemorySize, SM4);
    cudaFuncSetAttribute(gemm_split_t<2>, cudaFuncAttributeMaxDynamicSharedMemorySize, SM2);
    cudaFuncSetAttribute(gemm_qkv,        cudaFuncAttributeMaxDynamicSharedMemorySize, SM2);
    cudaFuncSetAttribute(flash_split,     cudaFuncAttributeMaxDynamicSharedMemorySize, F_SMEM);

    transp_split<<<dim3(64, 64, 12), 256>>>(Wq, Wk, Wv, Wo, W1, W2);
    split_x<<<ROWS * D_MODEL / 1024, 256>>>(x_in);

    const dim3 gQKV(D_MODEL / 64, ROWS / 128, 3);      // (8, 32, 3)
    const dim3 gProj64(D_MODEL / 64, ROWS / 128);      // (8, 32)
    const dim3 gFF1(D_FF / 128, ROWS / 128);           // (16, 32)
    const dim3 gFlash(2 * SEQ / 128, BH);              // (32, 16)
    const dim3 gVT(SEQ / 32, BH);                      // (64, 16)

    for (int l = 0; l < 2; l++) {
        const int wOff   = l * D_MODEL * D_MODEL;
        const int w1Off  = l * D_MODEL * D_FF;
        const size_t bOff  = (size_t)l * D_MODEL;
        const size_t b1Off = (size_t)l * D_FF;

        gemm_qkv<<<gQKV, 256, SM2>>>(bq + bOff, bk + bOff, bv + bOff, wOff);
        vtransp<<<gVT, 256>>>();
        flash_split<<<gFlash, 256, F_SMEM>>>(tau, delta);
        merge_k<<<ROWS * D_MODEL / 512, 256>>>();

        gemm_split_t<2><<<gProj64, 256, SM2>>>(aath, wo_h + wOff,
                                               bo + bOff, gx, gx, nullptr,
                                               D_MODEL, D_MODEL, 1);
        ln_k<<<ROWS / 2, 256>>>(gx, ln1g + bOff, ln1b + bOff, gxb, axbh);

        gemm_split_t<4><<<gFF1, 256, SM4>>>(axbh, w1_h + w1Off,
                                            b1 + b1Off, nullptr, nullptr, ahh,
                                            D_FF, D_MODEL, 2);
        gemm_split_t<2><<<gProj64, 256, SM2>>>(ahh, w2_h + w1Off,
                                               b2 + bOff, gxb, go, nullptr,
                                               D_MODEL, D_FF, 1);
        ln_k<<<ROWS / 2, 256>>>(go, ln2g + bOff, ln2b + bOff, gx, axh);
    }
    ln_k<<<ROWS / 2, 256>>>(gx, lnfg, lnfb, (float*)d_out, nullptr);
}